// round 10
// baseline (speedup 1.0000x reference)
#include <cuda_runtime.h>
#include <cuda_bf16.h>
#include <math.h>
#include <stdint.h>

#define N 2048
#define D 16384
#define NB 128
#define LDA 129            // padded smem stride (bank-conflict-free columns)
#define NBLK 16            // N / NB
#define PI_F 3.14159265358979323846f

// ---------------- device scratch (no allocations allowed) ----------------
__device__ float g_S[(size_t)N * N];        // gram / sigma / L (lower, in place)
__device__ float g_W[(size_t)N * N];        // L^{-1} (lower)
__device__ float g_invD[NBLK * NB * NB];    // per-panel inv(L11)
__device__ float g_T2[(size_t)1024 * 1024]; // D&C inversion scratch
__device__ float g_diag[N];                 // diag snapshot
__device__ float g_scal[4];                 // [0]=trace acc, [1]=proj acc
__device__ int8_t g_a8[(size_t)N * D];      // x high part (x ~ a/16 + b/2048)
__device__ int8_t g_b8[(size_t)N * D];      // x low part
__device__ __nv_bfloat16 g_Phi[(size_t)N * NB];  // TRSM panel, bf16 hi
__device__ __nv_bfloat16 g_Plo[(size_t)N * NB];  // TRSM panel, bf16 lo

// ==========================================================================
__device__ __forceinline__ uint32_t smem_u32(const void* p) {
    uint32_t a;
    asm("{ .reg .u64 t; cvta.to.shared.u64 t, %1; cvt.u32.u64 %0, t; }"
        : "=r"(a) : "l"(p));
    return a;
}

// ==========================================================================
// quantization: x -> a (int8, scale 1/16) + b (int8, scale 1/2048)
// x ~= a/16 + b/2048, |err| <= 2^-12
// ==========================================================================
__global__ void quant_kernel(const float* __restrict__ x)
{
    size_t total = (size_t)N * D;
    for (size_t i = blockIdx.x * (size_t)blockDim.x + threadIdx.x; i < total;
         i += (size_t)gridDim.x * blockDim.x) {
        float v = fminf(fmaxf(x[i], -7.9f), 7.9f);
        float fa = rintf(v * 16.f);
        fa = fminf(fmaxf(fa, -127.f), 127.f);
        float fb = rintf((v - fa * 0.0625f) * 2048.f);
        fb = fminf(fmaxf(fb, -127.f), 127.f);
        g_a8[i] = (int8_t)fa;
        g_b8[i] = (int8_t)fb;
    }
}

// ==========================================================================
// int8 tensor-core gram over lower 128x128 tile pairs:
//   AA += a_i . a_j^T ;  AB += a_i . b_j^T + b_i . a_j^T   (int32, exact)
//   sigma = clip(AA/(256 D) + AB/(32768 D), -1, 1)
// ==========================================================================
#define QK 64                        // K elems per stage (64 int8 bytes/row)
#define QSTRIDE 80                   // smem bytes per row (64 + 16 pad)
#define QTILE_B (128 * QSTRIDE)      // 10240 B per operand tile
#define QSMEM (2 * 4 * QTILE_B)      // 81920 B

__device__ __forceinline__ void ldsm_x4(uint32_t* r, uint32_t addr) {
    asm volatile("ldmatrix.sync.aligned.m8n8.x4.shared.b16 {%0,%1,%2,%3}, [%4];"
                 : "=r"(r[0]), "=r"(r[1]), "=r"(r[2]), "=r"(r[3]) : "r"(addr));
}
__device__ __forceinline__ void ldsm_x2(uint32_t* r, uint32_t addr) {
    asm volatile("ldmatrix.sync.aligned.m8n8.x2.shared.b16 {%0,%1}, [%2];"
                 : "=r"(r[0]), "=r"(r[1]) : "r"(addr));
}
__device__ __forceinline__ void mma_s8(int32_t* d, const uint32_t* a,
                                       const uint32_t* b) {
    asm volatile(
        "mma.sync.aligned.m16n8k32.row.col.s32.s8.s8.s32 "
        "{%0,%1,%2,%3}, {%4,%5,%6,%7}, {%8,%9}, {%0,%1,%2,%3};"
        : "+r"(d[0]), "+r"(d[1]), "+r"(d[2]), "+r"(d[3])
        : "r"(a[0]), "r"(a[1]), "r"(a[2]), "r"(a[3]), "r"(b[0]), "r"(b[1]));
}
#define CP_ASYNC(dst, src) \
    asm volatile("cp.async.cg.shared.global [%0], [%1], 16;" \
                 :: "r"(dst), "l"(src))
#define CP_COMMIT() asm volatile("cp.async.commit_group;" ::: "memory")

__global__ __launch_bounds__(256, 1)
void gram_i8_kernel(float* __restrict__ Cbase)
{
    extern __shared__ char dsm[];
    uint32_t sbase = smem_u32(dsm);

    int tid  = threadIdx.x;
    int wid  = tid >> 5;
    int lane = tid & 31;

    int t = blockIdx.x;
    int bi = (int)((sqrtf(8.f * (float)t + 1.f) - 1.f) * 0.5f);
    while ((bi + 1) * (bi + 2) / 2 <= t) bi++;
    while (bi * (bi + 1) / 2 > t) bi--;
    int bj = t - bi * (bi + 1) / 2;

    const int8_t* srcs[4] = {
        g_a8 + (size_t)bi * 128 * D,   // Aa
        g_b8 + (size_t)bi * 128 * D,   // Ab
        g_a8 + (size_t)bj * 128 * D,   // Ba
        g_b8 + (size_t)bj * 128 * D    // Bb
    };

    int m0w = (wid & 1) * 64;
    int n0w = (wid >> 1) * 32;

    int32_t accAA[4][4][4], accAB[4][4][4];
#pragma unroll
    for (int im = 0; im < 4; im++)
#pragma unroll
        for (int jn = 0; jn < 4; jn++)
#pragma unroll
            for (int e = 0; e < 4; e++) { accAA[im][jn][e] = 0; accAB[im][jn][e] = 0; }

    const int S = D / QK;   // 256 stages

    {
#pragma unroll
        for (int it = 0; it < 8; it++) {
            int idx = tid + it * 256;
            int tile = idx >> 9;
            int rem = idx & 511;
            int r = rem >> 2, ch = rem & 3;
            uint32_t dst = sbase + (uint32_t)tile * QTILE_B + r * QSTRIDE + ch * 16;
            CP_ASYNC(dst, srcs[tile] + (size_t)r * D + ch * 16);
        }
        CP_COMMIT();
    }

#pragma unroll 1
    for (int s = 0; s < S; s++) {
        if (s + 1 < S) {
            int k0 = (s + 1) * QK;
            uint32_t boff = (uint32_t)((s + 1) & 1) * (4 * QTILE_B);
#pragma unroll
            for (int it = 0; it < 8; it++) {
                int idx = tid + it * 256;
                int tile = idx >> 9;
                int rem = idx & 511;
                int r = rem >> 2, ch = rem & 3;
                uint32_t dst = sbase + boff + (uint32_t)tile * QTILE_B +
                               r * QSTRIDE + ch * 16;
                CP_ASYNC(dst, srcs[tile] + (size_t)r * D + k0 + ch * 16);
            }
            CP_COMMIT();
            asm volatile("cp.async.wait_group 1;" ::: "memory");
        } else {
            asm volatile("cp.async.wait_group 0;" ::: "memory");
        }
        __syncthreads();

        uint32_t buf = sbase + (uint32_t)(s & 1) * (4 * QTILE_B);
        uint32_t Aa_b = buf;
        uint32_t Ab_b = buf + QTILE_B;
        uint32_t Ba_b = buf + 2 * QTILE_B;
        uint32_t Bb_b = buf + 3 * QTILE_B;

#pragma unroll
        for (int ks = 0; ks < 2; ks++) {
            int kof = ks * 32;               // byte offset of this k32 chunk
            int arow = lane & 15;
            int acol = kof + ((lane >> 4) << 4);
            uint32_t aa[4][4], ab[4][4];
#pragma unroll
            for (int im = 0; im < 4; im++) {
                uint32_t ro = (uint32_t)(m0w + im * 16 + arow) * QSTRIDE + acol;
                ldsm_x4(aa[im], Aa_b + ro);
                ldsm_x4(ab[im], Ab_b + ro);
            }
            int brow = lane & 7;
            int bcol = kof + (((lane >> 3) & 1) << 4);
            uint32_t ba[4][2], bb[4][2];
#pragma unroll
            for (int jn = 0; jn < 4; jn++) {
                uint32_t ro = (uint32_t)(n0w + jn * 8 + brow) * QSTRIDE + bcol;
                ldsm_x2(ba[jn], Ba_b + ro);
                ldsm_x2(bb[jn], Bb_b + ro);
            }
#pragma unroll
            for (int im = 0; im < 4; im++)
#pragma unroll
                for (int jn = 0; jn < 4; jn++) {
                    mma_s8(accAA[im][jn], aa[im], ba[jn]);
                    mma_s8(accAB[im][jn], aa[im], bb[jn]);
                    mma_s8(accAB[im][jn], ab[im], ba[jn]);
                }
        }
        __syncthreads();
    }

    const float c1 = 1.0f / (256.0f * (float)D);
    const float c2 = 1.0f / (32768.0f * (float)D);
#pragma unroll
    for (int im = 0; im < 4; im++) {
        int row = bi * 128 + m0w + im * 16 + (lane >> 2);
#pragma unroll
        for (int jn = 0; jn < 4; jn++) {
            int col = bj * 128 + n0w + jn * 8 + (lane & 3) * 2;
            float v0 = (float)accAA[im][jn][0] * c1 + (float)accAB[im][jn][0] * c2;
            float v1 = (float)accAA[im][jn][1] * c1 + (float)accAB[im][jn][1] * c2;
            float v2 = (float)accAA[im][jn][2] * c1 + (float)accAB[im][jn][2] * c2;
            float v3 = (float)accAA[im][jn][3] * c1 + (float)accAB[im][jn][3] * c2;
            Cbase[(size_t)row * N + col]           = fminf(fmaxf(v0, -1.f), 1.f);
            Cbase[(size_t)row * N + col + 1]       = fminf(fmaxf(v1, -1.f), 1.f);
            Cbase[(size_t)(row + 8) * N + col]     = fminf(fmaxf(v2, -1.f), 1.f);
            Cbase[(size_t)(row + 8) * N + col + 1] = fminf(fmaxf(v3, -1.f), 1.f);
        }
    }
}

// ==========================================================================
// bf16-split NT mma kernel over lower tile pairs (used for trailing SYRK):
//   C -= Ahi*Bhi^T + Ahi*Blo^T + Alo*Bhi^T
// ==========================================================================
#define BKG 32
#define GTILE_B (128 * 40 * 2)
#define GRAM_SMEM (2 * 4 * GTILE_B)

__device__ __forceinline__ void mma_bf16(float* d, const uint32_t* a,
                                         const uint32_t* b) {
    asm volatile(
        "mma.sync.aligned.m16n8k16.row.col.f32.bf16.bf16.f32 "
        "{%0,%1,%2,%3}, {%4,%5,%6,%7}, {%8,%9}, {%0,%1,%2,%3};"
        : "+f"(d[0]), "+f"(d[1]), "+f"(d[2]), "+f"(d[3])
        : "r"(a[0]), "r"(a[1]), "r"(a[2]), "r"(a[3]), "r"(b[0]), "r"(b[1]));
}

__global__ __launch_bounds__(256, 1)
void mma_nt_kernel(const __nv_bfloat16* __restrict__ Ahi,
                   const __nv_bfloat16* __restrict__ Alo,
                   const __nv_bfloat16* __restrict__ Bhi,
                   const __nv_bfloat16* __restrict__ Blo,
                   size_t lda, float* __restrict__ Cbase, int ldc, int K)
{
    extern __shared__ char dsm[];
    uint32_t sbase = smem_u32(dsm);

    int tid  = threadIdx.x;
    int wid  = tid >> 5;
    int lane = tid & 31;

    int t = blockIdx.x;
    int bi = (int)((sqrtf(8.f * (float)t + 1.f) - 1.f) * 0.5f);
    while ((bi + 1) * (bi + 2) / 2 <= t) bi++;
    while (bi * (bi + 1) / 2 > t) bi--;
    int bj = t - bi * (bi + 1) / 2;

    const __nv_bfloat16* srcs[4] = {
        Ahi + (size_t)bi * 128 * lda,
        Alo + (size_t)bi * 128 * lda,
        Bhi + (size_t)bj * 128 * lda,
        Blo + (size_t)bj * 128 * lda
    };

    int m0w = (wid & 1) * 64;
    int n0w = (wid >> 1) * 32;

    float acc[4][4][4];
#pragma unroll
    for (int im = 0; im < 4; im++)
#pragma unroll
        for (int jn = 0; jn < 4; jn++)
#pragma unroll
            for (int e = 0; e < 4; e++) acc[im][jn][e] = 0.f;

    const int S = K / BKG;

    {
#pragma unroll
        for (int it = 0; it < 8; it++) {
            int idx = tid + it * 256;
            int tile = idx >> 9;
            int rem = idx & 511;
            int r = rem >> 2, ch = rem & 3;
            uint32_t dst = sbase + (uint32_t)tile * GTILE_B + r * 80 + ch * 16;
            CP_ASYNC(dst, srcs[tile] + (size_t)r * lda + ch * 8);
        }
        CP_COMMIT();
    }

#pragma unroll 1
    for (int s = 0; s < S; s++) {
        if (s + 1 < S) {
            int k0 = (s + 1) * BKG;
            uint32_t boff = (uint32_t)((s + 1) & 1) * (4 * GTILE_B);
#pragma unroll
            for (int it = 0; it < 8; it++) {
                int idx = tid + it * 256;
                int tile = idx >> 9;
                int rem = idx & 511;
                int r = rem >> 2, ch = rem & 3;
                uint32_t dst = sbase + boff + (uint32_t)tile * GTILE_B +
                               r * 80 + ch * 16;
                CP_ASYNC(dst, srcs[tile] + (size_t)r * lda + k0 + ch * 8);
            }
            CP_COMMIT();
            asm volatile("cp.async.wait_group 1;" ::: "memory");
        } else {
            asm volatile("cp.async.wait_group 0;" ::: "memory");
        }
        __syncthreads();

        uint32_t buf = sbase + (uint32_t)(s & 1) * (4 * GTILE_B);
        uint32_t Ahi_b = buf;
        uint32_t Alo_b = buf + GTILE_B;
        uint32_t Bhi_b = buf + 2 * GTILE_B;
        uint32_t Blo_b = buf + 3 * GTILE_B;

#pragma unroll
        for (int ks = 0; ks < 2; ks++) {
            int kof = ks * 16;
            int arow = lane & 15;
            int acol = kof + 8 * (lane >> 4);
            uint32_t ah[4][4], al[4][4];
#pragma unroll
            for (int im = 0; im < 4; im++) {
                uint32_t ro = (uint32_t)(m0w + im * 16 + arow) * 80 + acol * 2;
                ldsm_x4(ah[im], Ahi_b + ro);
                ldsm_x4(al[im], Alo_b + ro);
            }
            int brow = lane & 7;
            int bcol = kof + 8 * ((lane >> 3) & 1);
            uint32_t bh[4][2], bl[4][2];
#pragma unroll
            for (int jn = 0; jn < 4; jn++) {
                uint32_t ro = (uint32_t)(n0w + jn * 8 + brow) * 80 + bcol * 2;
                ldsm_x2(bh[jn], Bhi_b + ro);
                ldsm_x2(bl[jn], Blo_b + ro);
            }
#pragma unroll
            for (int im = 0; im < 4; im++)
#pragma unroll
                for (int jn = 0; jn < 4; jn++) {
                    mma_bf16(acc[im][jn], ah[im], bh[jn]);
                    mma_bf16(acc[im][jn], ah[im], bl[jn]);
                    mma_bf16(acc[im][jn], al[im], bh[jn]);
                }
        }
        __syncthreads();
    }

#pragma unroll
    for (int im = 0; im < 4; im++) {
        int row = bi * 128 + m0w + im * 16 + (lane >> 2);
#pragma unroll
        for (int jn = 0; jn < 4; jn++) {
            int col = bj * 128 + n0w + jn * 8 + (lane & 3) * 2;
            float* p0 = Cbase + (size_t)row * ldc + col;
            float* p1 = Cbase + (size_t)(row + 8) * ldc + col;
            p0[0] -= acc[im][jn][0];
            p0[1] -= acc[im][jn][1];
            p1[0] -= acc[im][jn][2];
            p1[1] -= acc[im][jn][3];
        }
    }
}

// ==========================================================================
__global__ void diag_kernel()
{
    int i = blockIdx.x * blockDim.x + threadIdx.x;
    if (i < N) g_diag[i] = g_S[(size_t)i * N + i];
}

__global__ void step_kernel(const float* __restrict__ alpha_p)
{
    int j = blockIdx.x * 32 + threadIdx.x;
    int i = blockIdx.y * 8 + threadIdx.y;
    if (i >= N || j > i) return;
    float a  = *alpha_p;
    float a2 = a * a;
    float cross = sqrtf(g_diag[i] * g_diag[j]);
    float s = g_S[(size_t)i * N + j];
    float m = fminf(fmaxf(s / cross, -1.f), 1.f);
    float q = 1.f - m * m;
    float sq, ac;
    if (q > 0.f) { sq = sqrtf(q); ac = acosf(m); }
    else         { sq = 0.f;      ac = (m > 0.f) ? 0.f : PI_F; }
    float f  = (sq + m * (PI_F - ac)) / PI_F;
    float ts = cross * f;
    float ov = (s + a2 * ts) / (1.f + a2);
    g_S[(size_t)i * N + j] = fminf(fmaxf(ov, -1.f), 1.f);
}

// ==========================================================================
// panel factorization + inversion of 128x128 diag block.
// ==========================================================================
__global__ __launch_bounds__(256, 1)
void potrf_invert(int kb)
{
    extern __shared__ float sh[];
    float* A = sh;                 // NB x NB stride LDA (L, lower)
    float* W = sh + NB * LDA;      // NB x NB stride LDA (inv(L), lower)
    __shared__ float Ts[3 * 1056];
    int tid = threadIdx.x;
    int base = kb * NB;

    for (int idx = tid; idx < NB * 32; idx += 256) {
        int i = idx >> 5, j4 = (idx & 31) << 2;
        float4 v = *(const float4*)&g_S[(size_t)(base + i) * N + base + j4];
        A[i * LDA + j4 + 0] = v.x;
        A[i * LDA + j4 + 1] = v.y;
        A[i * LDA + j4 + 2] = v.z;
        A[i * LDA + j4 + 3] = v.w;
    }
    __syncthreads();

    for (int p = 0; p < 4; p++) {
        int off = p * 32;

        if (tid < 32) {
            const unsigned FULL = 0xffffffffu;
            int r = tid;
            float ar[32];
#pragma unroll
            for (int t = 0; t < 32; t++)
                ar[t] = (t <= r) ? A[(off + r) * LDA + off + t] : 0.f;
            float rs_reg = 0.f;
#pragma unroll
            for (int j = 0; j < 32; j++) {
                float d   = __shfl_sync(FULL, ar[j], j);
                float rsj = rsqrtf(d);
                float lj  = ar[j] * rsj;
                ar[j] = lj;
                if (r == j) rs_reg = rsj;
#pragma unroll
                for (int t = j + 1; t < 32; t++) {
                    float ltj = __shfl_sync(FULL, lj, t);
                    ar[t] -= lj * ltj;
                }
            }
            int c = r;
            float w[32];
#pragma unroll
            for (int t = 0; t < 32; t++) w[t] = 0.f;
#pragma unroll
            for (int i = 0; i < 32; i++) {
                float s = (i == c) ? 1.f : 0.f;
#pragma unroll
                for (int t = 0; t < i; t++) {
                    float lit = __shfl_sync(FULL, ar[t], i);
                    s -= lit * w[t];
                }
                float rsi = __shfl_sync(FULL, rs_reg, i);
                w[i] = (i >= c) ? s * rsi : 0.f;
            }
#pragma unroll
            for (int t = 0; t < 32; t++)
                if (t <= r) A[(off + r) * LDA + off + t] = ar[t];
#pragma unroll
            for (int i = 0; i < 32; i++)
                W[(off + i) * LDA + off + c] = w[i];
        }
        __syncthreads();

        int nr = NB - off - 32;
        if (nr > 0) {
            int ntr = (nr >> 2) * 8;
            float acc[4][4];
            int tr = 0, tc = 0;
            if (tid < ntr) {
                tr = (tid >> 3) * 4;
                tc = (tid & 7) * 4;
#pragma unroll
                for (int r = 0; r < 4; r++)
#pragma unroll
                    for (int cidx = 0; cidx < 4; cidx++) acc[r][cidx] = 0.f;
#pragma unroll 8
                for (int k = 0; k < 32; k++) {
                    float av[4], wv[4];
#pragma unroll
                    for (int r = 0; r < 4; r++)
                        av[r] = A[(off + 32 + tr + r) * LDA + off + k];
#pragma unroll
                    for (int cidx = 0; cidx < 4; cidx++)
                        wv[cidx] = W[(off + tc + cidx) * LDA + off + k];
#pragma unroll
                    for (int r = 0; r < 4; r++)
#pragma unroll
                        for (int cidx = 0; cidx < 4; cidx++)
                            acc[r][cidx] += av[r] * wv[cidx];
                }
            }
            __syncthreads();
            if (tid < ntr) {
#pragma unroll
                for (int r = 0; r < 4; r++)
#pragma unroll
                    for (int cidx = 0; cidx < 4; cidx++)
                        A[(off + 32 + tr + r) * LDA + off + tc + cidx] =
                            acc[r][cidx];
            }
            __syncthreads();

            int nt = nr >> 2;
            int ntot = nt * (nt + 1) / 2;
            for (int tId = tid; tId < ntot; tId += 256) {
                int ti = (int)((sqrtf(8.f * (float)tId + 1.f) - 1.f) * 0.5f);
                while ((ti + 1) * (ti + 2) / 2 <= tId) ti++;
                while (ti * (ti + 1) / 2 > tId) ti--;
                int tj = tId - ti * (ti + 1) / 2;
                int i0 = off + 32 + ti * 4;
                int t0 = off + 32 + tj * 4;
                float a2[4][4];
#pragma unroll
                for (int r = 0; r < 4; r++)
#pragma unroll
                    for (int cidx = 0; cidx < 4; cidx++) a2[r][cidx] = 0.f;
#pragma unroll 8
                for (int k = 0; k < 32; k++) {
                    float av[4], bv[4];
#pragma unroll
                    for (int r = 0; r < 4; r++)
                        av[r] = A[(i0 + r) * LDA + off + k];
#pragma unroll
                    for (int cidx = 0; cidx < 4; cidx++)
                        bv[cidx] = A[(t0 + cidx) * LDA + off + k];
#pragma unroll
                    for (int r = 0; r < 4; r++)
#pragma unroll
                        for (int cidx = 0; cidx < 4; cidx++)
                            a2[r][cidx] += av[r] * bv[cidx];
                }
#pragma unroll
                for (int r = 0; r < 4; r++)
#pragma unroll
                    for (int cidx = 0; cidx < 4; cidx++) {
                        int ii = i0 + r, tt = t0 + cidx;
                        if (tt <= ii) A[ii * LDA + tt] -= a2[r][cidx];
                    }
            }
            __syncthreads();
        }
    }

    for (int ib = 1; ib < 4; ib++) {
        for (int tId = tid; tId < ib * 64; tId += 256) {
            int j = tId >> 6;
            int e = tId & 63;
            int r0 = (e >> 3) * 4, c0 = (e & 7) * 4;
            float acc[4][4];
#pragma unroll
            for (int r = 0; r < 4; r++)
#pragma unroll
                for (int cidx = 0; cidx < 4; cidx++) acc[r][cidx] = 0.f;
            for (int tb = j; tb < ib; tb++) {
#pragma unroll 8
                for (int k = 0; k < 32; k++) {
                    float lv[4], wv[4];
#pragma unroll
                    for (int r = 0; r < 4; r++)
                        lv[r] = A[(32 * ib + r0 + r) * LDA + 32 * tb + k];
#pragma unroll
                    for (int cidx = 0; cidx < 4; cidx++)
                        wv[cidx] = W[(32 * tb + k) * LDA + 32 * j + c0 + cidx];
#pragma unroll
                    for (int r = 0; r < 4; r++)
#pragma unroll
                        for (int cidx = 0; cidx < 4; cidx++)
                            acc[r][cidx] += lv[r] * wv[cidx];
                }
            }
#pragma unroll
            for (int r = 0; r < 4; r++)
#pragma unroll
                for (int cidx = 0; cidx < 4; cidx++)
                    Ts[j * 1056 + (r0 + r) * 33 + c0 + cidx] = acc[r][cidx];
        }
        __syncthreads();
        for (int tId = tid; tId < ib * 64; tId += 256) {
            int j = tId >> 6;
            int e = tId & 63;
            int r0 = (e >> 3) * 4, c0 = (e & 7) * 4;
            float acc[4][4];
#pragma unroll
            for (int r = 0; r < 4; r++)
#pragma unroll
                for (int cidx = 0; cidx < 4; cidx++) acc[r][cidx] = 0.f;
#pragma unroll 8
            for (int k = 0; k < 32; k++) {
                float wv[4], tv[4];
#pragma unroll
                for (int r = 0; r < 4; r++)
                    wv[r] = W[(32 * ib + r0 + r) * LDA + 32 * ib + k];
#pragma unroll
                for (int cidx = 0; cidx < 4; cidx++)
                    tv[cidx] = Ts[j * 1056 + k * 33 + c0 + cidx];
#pragma unroll
                for (int r = 0; r < 4; r++)
#pragma unroll
                    for (int cidx = 0; cidx < 4; cidx++)
                        acc[r][cidx] += wv[r] * tv[cidx];
            }
#pragma unroll
            for (int r = 0; r < 4; r++)
#pragma unroll
                for (int cidx = 0; cidx < 4; cidx++)
                    W[(32 * ib + r0 + r) * LDA + 32 * j + c0 + cidx] =
                        -acc[r][cidx];
        }
        __syncthreads();
    }

    for (int idx = tid; idx < NB * NB; idx += 256) {
        int i = idx >> 7, j = idx & 127;
        if (j <= i) g_S[(size_t)(base + i) * N + base + j] = A[i * LDA + j];
        g_invD[(size_t)kb * NB * NB + idx] =
            ((j >> 5) <= (i >> 5)) ? W[i * LDA + j] : 0.f;
    }
}

// ==========================================================================
// TRSM panel GEMM: C = A * B^T (64x64 tiles); writes fp32 L into S and
// bf16 hi/lo split panels for the mma SYRK.
// ==========================================================================
__global__ __launch_bounds__(256, 2)
void gemm_nt_split(const float* __restrict__ A, int lda,
                   const float* __restrict__ B, int ldb,
                   float* __restrict__ Cs, int ldcs,
                   __nv_bfloat16* __restrict__ Phi,
                   __nv_bfloat16* __restrict__ Plo, int K)
{
    __shared__ float As[16][64];
    __shared__ float Bs[16][64];
    int bi = blockIdx.y, bj = blockIdx.x;
    int tid = threadIdx.x;
    int tx = tid & 15, ty = tid >> 4;

    const float* Ab = A + (size_t)(bi * 64) * lda;
    const float* Bb = B + (size_t)(bj * 64) * ldb;

    int arow = tid >> 2, akk = (tid & 3) << 2;

    float acc[4][4];
#pragma unroll
    for (int i = 0; i < 4; i++)
#pragma unroll
        for (int j = 0; j < 4; j++) acc[i][j] = 0.f;

    for (int k0 = 0; k0 < K; k0 += 16) {
        float4 va = *(const float4*)(Ab + (size_t)arow * lda + k0 + akk);
        float4 vb = *(const float4*)(Bb + (size_t)arow * ldb + k0 + akk);
        As[akk + 0][arow] = va.x; As[akk + 1][arow] = va.y;
        As[akk + 2][arow] = va.z; As[akk + 3][arow] = va.w;
        Bs[akk + 0][arow] = vb.x; Bs[akk + 1][arow] = vb.y;
        Bs[akk + 2][arow] = vb.z; Bs[akk + 3][arow] = vb.w;
        __syncthreads();
#pragma unroll
        for (int kk = 0; kk < 16; kk++) {
            float4 a = *(const float4*)&As[kk][ty * 4];
            float4 b = *(const float4*)&Bs[kk][tx * 4];
            float av[4] = {a.x, a.y, a.z, a.w};
            float bv[4] = {b.x, b.y, b.z, b.w};
#pragma unroll
            for (int i = 0; i < 4; i++)
#pragma unroll
                for (int j = 0; j < 4; j++)
                    acc[i][j] += av[i] * bv[j];
        }
        __syncthreads();
    }

#pragma unroll
    for (int i = 0; i < 4; i++) {
        int row = bi * 64 + ty * 4 + i;
#pragma unroll
        for (int j = 0; j < 4; j++) {
            int col = bj * 64 + tx * 4 + j;
            float v = acc[i][j];
            Cs[(size_t)row * ldcs + col] = v;
            __nv_bfloat16 h = __float2bfloat16(v);
            Phi[(size_t)row * NB + col] = h;
            Plo[(size_t)row * NB + col] =
                __float2bfloat16(v - __bfloat162float(h));
        }
    }
}

// ==========================================================================
// batched NN GEMM, 128x128 tiles / 8x8 micro-tiles (for D&C inversion)
// ==========================================================================
__global__ __launch_bounds__(256, 1)
void gemm_nn_b128(const float* __restrict__ A, size_t strA, int lda,
                  const float* __restrict__ B, size_t strB, int ldb,
                  float* __restrict__ C, size_t strC, int ldc,
                  int K, float alpha)
{
    A += (size_t)blockIdx.z * strA;
    B += (size_t)blockIdx.z * strB;
    C += (size_t)blockIdx.z * strC;

    __shared__ float As[8][128];
    __shared__ float Bs[8][128];

    int bi = blockIdx.y, bj = blockIdx.x;
    int tid = threadIdx.x;
    int tx = tid & 15, ty = tid >> 4;

    int lrow = tid >> 1;
    int lkk  = (tid & 1) * 4;
    int brow = tid >> 5;
    int bcol = (tid & 31) * 4;

    const float* Ap = A + (size_t)(bi * 128 + lrow) * lda + lkk;
    const float* Bp = B + bj * 128 + bcol;

    float acc[8][8];
#pragma unroll
    for (int i = 0; i < 8; i++)
#pragma unroll
        for (int j = 0; j < 8; j++) acc[i][j] = 0.f;

    for (int k0 = 0; k0 < K; k0 += 8) {
        float4 va = *(const float4*)(Ap + k0);
        float4 vb = *(const float4*)(Bp + (size_t)(k0 + brow) * ldb);
        if (k0) __syncthreads();
        As[lkk + 0][lrow] = va.x; As[lkk + 1][lrow] = va.y;
        As[lkk + 2][lrow] = va.z; As[lkk + 3][lrow] = va.w;
        *(float4*)&Bs[brow][bcol] = vb;
        __syncthreads();
#pragma unroll
        for (int kk = 0; kk < 8; kk++) {
            float4 a0 = *(const float4*)&As[kk][ty * 4];
            float4 a1 = *(const float4*)&As[kk][64 + ty * 4];
            float4 b0 = *(const float4*)&Bs[kk][tx * 4];
            float4 b1 = *(const float4*)&Bs[kk][64 + tx * 4];
            float a[8] = {a0.x, a0.y, a0.z, a0.w, a1.x, a1.y, a1.z, a1.w};
            float b[8] = {b0.x, b0.y, b0.z, b0.w, b1.x, b1.y, b1.z, b1.w};
#pragma unroll
            for (int i = 0; i < 8; i++)
#pragma unroll
                for (int j = 0; j < 8; j++)
                    acc[i][j] += a[i] * b[j];
        }
    }

#pragma unroll
    for (int i = 0; i < 8; i++) {
        int r = bi * 128 + ((i < 4) ? ty * 4 + i : 64 + ty * 4 + (i - 4));
#pragma unroll
        for (int j = 0; j < 8; j++) {
            int cc = bj * 128 + ((j < 4) ? tx * 4 + j : 64 + tx * 4 + (j - 4));
            C[(size_t)r * ldc + cc] = alpha * acc[i][j];
        }
    }
}

// ==========================================================================
__global__ void zero_kernel(float* p, int n)
{
    for (int i = blockIdx.x * blockDim.x + threadIdx.x; i < n;
         i += gridDim.x * blockDim.x)
        p[i] = 0.f;
}

__global__ void copy_diag_kernel()
{
    int kb = blockIdx.y;
    int idx = blockIdx.x * 256 + threadIdx.x;
    int i = idx >> 7, j = idx & 127;
    g_W[(size_t)(kb * NB + i) * N + kb * NB + j] =
        g_invD[(size_t)kb * NB * NB + idx];
}

__global__ void fnorm_kernel()
{
    __shared__ float red[256];
    float s = 0.f;
    size_t total = (size_t)N * N;
    for (size_t i = blockIdx.x * blockDim.x + threadIdx.x; i < total;
         i += (size_t)gridDim.x * blockDim.x) {
        float v = g_W[i];
        s += v * v;
    }
    red[threadIdx.x] = s; __syncthreads();
    for (int o = 128; o > 0; o >>= 1) {
        if (threadIdx.x < o) red[threadIdx.x] += red[threadIdx.x + o];
        __syncthreads();
    }
    if (threadIdx.x == 0) atomicAdd(&g_scal[0], red[0]);
}

__global__ void proj_kernel(const float* __restrict__ c)
{
    __shared__ float red[256];
    int r = blockIdx.x;
    const float* row = g_W + (size_t)r * N;
    float s = 0.f;
    for (int j = threadIdx.x; j < N; j += 256) s += row[j] * c[j];
    red[threadIdx.x] = s; __syncthreads();
    for (int o = 128; o > 0; o >>= 1) {
        if (threadIdx.x < o) red[threadIdx.x] += red[threadIdx.x + o];
        __syncthreads();
    }
    if (threadIdx.x == 0) {
        float y = red[0];
        atomicAdd(&g_scal[1], y * y);
    }
}

__global__ void final_kernel(float* out)
{
    __shared__ float red[256];
    float s = 0.f;
    for (int i = threadIdx.x; i < N; i += 256)
        s += logf(g_S[(size_t)i * N + i]);
    red[threadIdx.x] = s; __syncthreads();
    for (int o = 128; o > 0; o >>= 1) {
        if (threadIdx.x < o) red[threadIdx.x] += red[threadIdx.x + o];
        __syncthreads();
    }
    if (threadIdx.x == 0) {
        float nrd = expf(red[0] * (2.0f / (float)N));
        out[0] = (float)N / 5.0f +
                 nrd * ((0.5f - 1.0f / PI_F) * g_scal[0] + g_scal[1] / PI_F);
    }
}

// ==========================================================================
// host orchestration
// ==========================================================================
extern "C" void kernel_launch(void* const* d_in, const int* in_sizes, int n_in,
                              void* d_out, int out_size)
{
    (void)in_sizes; (void)n_in; (void)out_size;
    const float* x     = (const float*)d_in[0];
    const float* c     = (const float*)d_in[1];
    const float* alpha = (const float*)d_in[2];
    float* out = (float*)d_out;

    float *Sp, *Wp, *iDp, *T2p, *scalp;
    __nv_bfloat16 *Phip, *Plop;
    cudaGetSymbolAddress((void**)&Sp,    g_S);
    cudaGetSymbolAddress((void**)&Wp,    g_W);
    cudaGetSymbolAddress((void**)&iDp,   g_invD);
    cudaGetSymbolAddress((void**)&T2p,   g_T2);
    cudaGetSymbolAddress((void**)&scalp, g_scal);
    cudaGetSymbolAddress((void**)&Phip,  g_Phi);
    cudaGetSymbolAddress((void**)&Plop,  g_Plo);

    int potrf_smem = 2 * NB * LDA * (int)sizeof(float);
    cudaFuncSetAttribute(potrf_invert,
                         cudaFuncAttributeMaxDynamicSharedMemorySize,
                         potrf_smem);
    cudaFuncSetAttribute(mma_nt_kernel,
                         cudaFuncAttributeMaxDynamicSharedMemorySize,
                         GRAM_SMEM);
    cudaFuncSetAttribute(gram_i8_kernel,
                         cudaFuncAttributeMaxDynamicSharedMemorySize,
                         QSMEM);

    // 1. gram via int8 split mma (exact int32 accumulation)
    quant_kernel<<<4096, 256>>>(x);
    gram_i8_kernel<<<NBLK * (NBLK + 1) / 2, 256, QSMEM>>>(Sp);

    // 2. arc-cosine kernel step
    diag_kernel<<<N / 256, 256>>>();
    step_kernel<<<dim3(N / 32, N / 8), dim3(32, 8)>>>(alpha);

    // 3. blocked Cholesky (in place, lower)
    for (int k = 0; k < NBLK; k++) {
        potrf_invert<<<1, 256, potrf_smem>>>(k);
        if (k < NBLK - 1) {
            int rows = (NBLK - 1 - k) * NB;
            gemm_nt_split<<<dim3(2, rows / 64), 256>>>(
                Sp + (size_t)(k + 1) * NB * N + (size_t)k * NB, N,
                iDp + (size_t)k * NB * NB, NB,
                Sp + (size_t)(k + 1) * NB * N + (size_t)k * NB, N,
                Phip, Plop, NB);
            int T2 = NBLK - 1 - k;
            mma_nt_kernel<<<T2 * (T2 + 1) / 2, 256, GRAM_SMEM>>>(
                Phip, Plop, Phip, Plop, NB,
                Sp + (size_t)(k + 1) * NB * N + (size_t)(k + 1) * NB, N, NB);
        }
    }

    // 4. divide & conquer triangular inversion: W = L^{-1}
    zero_kernel<<<4096, 256>>>(Wp, N * N);
    copy_diag_kernel<<<dim3(64, NBLK), 256>>>();
    for (int lev = 0; lev < 4; lev++) {
        int s = 128 << lev;
        int pairs = N / (2 * s);
        size_t strW = (size_t)2 * s * (N + 1);
        gemm_nn_b128<<<dim3(s / 128, s / 128, pairs), 256>>>(
            Wp + (size_t)s * N + s, strW, N,
            Sp + (size_t)s * N,     strW, N,
            T2p, (size_t)s * s, s,
            s, 1.0f);
        gemm_nn_b128<<<dim3(s / 128, s / 128, pairs), 256>>>(
            T2p, (size_t)s * s, s,
            Wp, strW, N,
            Wp + (size_t)s * N, strW, N,
            s, -1.0f);
    }

    // 5. reductions + final scalar
    zero_kernel<<<1, 32>>>(scalp, 4);
    fnorm_kernel<<<1024, 256>>>();
    proj_kernel<<<N, 256>>>(c);
    final_kernel<<<1, 256>>>(out);
}

// round 11
// speedup vs baseline: 1.3800x; 1.3800x over previous
#include <cuda_runtime.h>
#include <cuda_bf16.h>
#include <math.h>
#include <stdint.h>

#define N 2048
#define D 16384
#define NB 128
#define LDA 129            // padded smem stride (bank-conflict-free columns)
#define NBLK 16            // N / NB
#define PI_F 3.14159265358979323846f

// ---------------- device scratch (no allocations allowed) ----------------
__device__ float g_S[(size_t)N * N];        // gram / sigma / L (lower, in place)
__device__ float g_W[(size_t)N * N];        // L^{-1} (lower)
__device__ float g_invD[NBLK * NB * NB];    // per-panel inv(L11)
__device__ float g_T2[(size_t)1024 * 1024]; // D&C inversion scratch
__device__ float g_diag[N];                 // diag snapshot
__device__ float g_scal[4];                 // [0]=trace acc, [1]=proj acc
__device__ __nv_bfloat16 g_hi[(size_t)N * D];
__device__ __nv_bfloat16 g_lo[(size_t)N * D];
__device__ __nv_bfloat16 g_Phi[(size_t)N * NB];  // TRSM panel, bf16 hi
__device__ __nv_bfloat16 g_Plo[(size_t)N * NB];  // TRSM panel, bf16 lo

// ==========================================================================
__device__ __forceinline__ uint32_t smem_u32(const void* p) {
    uint32_t a;
    asm("{ .reg .u64 t; cvta.to.shared.u64 t, %1; cvt.u32.u64 %0, t; }"
        : "=r"(a) : "l"(p));
    return a;
}

// ==========================================================================
// split conversion: x -> hi (bf16) + lo (bf16 of residual), vectorized
// ==========================================================================
__global__ void split_kernel(const float* __restrict__ x)
{
    size_t total = (size_t)N * D / 4;
    const float4* x4 = (const float4*)x;
    for (size_t i = blockIdx.x * (size_t)blockDim.x + threadIdx.x; i < total;
         i += (size_t)gridDim.x * blockDim.x) {
        float4 v = x4[i];
        __nv_bfloat16 h0 = __float2bfloat16(v.x);
        __nv_bfloat16 h1 = __float2bfloat16(v.y);
        __nv_bfloat16 h2 = __float2bfloat16(v.z);
        __nv_bfloat16 h3 = __float2bfloat16(v.w);
        __nv_bfloat162* hp = (__nv_bfloat162*)(g_hi + i * 4);
        __nv_bfloat162* lp = (__nv_bfloat162*)(g_lo + i * 4);
        hp[0] = __nv_bfloat162(h0, h1);
        hp[1] = __nv_bfloat162(h2, h3);
        lp[0] = __nv_bfloat162(__float2bfloat16(v.x - __bfloat162float(h0)),
                               __float2bfloat16(v.y - __bfloat162float(h1)));
        lp[1] = __nv_bfloat162(__float2bfloat16(v.z - __bfloat162float(h2)),
                               __float2bfloat16(v.w - __bfloat162float(h3)));
    }
}

// ==========================================================================
// unified bf16-split NT mma kernel over lower tile pairs:
// mode 0 (gram):  C = clip((Ahi*Bhi^T + Ahi*Blo^T) * scale, -1, 1)
//                 (2 products; dropped lo*hi term ~1e-5 abs, OK for sigma)
// mode 1 (SYRK):  C -= Ahi*Bhi^T + Ahi*Blo^T + Alo*Bhi^T  (3 products)
// ==========================================================================
#define BKG 32
#define GTILE_B (128 * 40 * 2)
#define GRAM_SMEM (2 * 4 * GTILE_B)

__device__ __forceinline__ void ldsm_x4(uint32_t* r, uint32_t addr) {
    asm volatile("ldmatrix.sync.aligned.m8n8.x4.shared.b16 {%0,%1,%2,%3}, [%4];"
                 : "=r"(r[0]), "=r"(r[1]), "=r"(r[2]), "=r"(r[3]) : "r"(addr));
}
__device__ __forceinline__ void ldsm_x2(uint32_t* r, uint32_t addr) {
    asm volatile("ldmatrix.sync.aligned.m8n8.x2.shared.b16 {%0,%1}, [%2];"
                 : "=r"(r[0]), "=r"(r[1]) : "r"(addr));
}
__device__ __forceinline__ void mma_bf16(float* d, const uint32_t* a,
                                         const uint32_t* b) {
    asm volatile(
        "mma.sync.aligned.m16n8k16.row.col.f32.bf16.bf16.f32 "
        "{%0,%1,%2,%3}, {%4,%5,%6,%7}, {%8,%9}, {%0,%1,%2,%3};"
        : "+f"(d[0]), "+f"(d[1]), "+f"(d[2]), "+f"(d[3])
        : "r"(a[0]), "r"(a[1]), "r"(a[2]), "r"(a[3]), "r"(b[0]), "r"(b[1]));
}
#define CP_ASYNC(dst, src) \
    asm volatile("cp.async.cg.shared.global [%0], [%1], 16;" \
                 :: "r"(dst), "l"(src))
#define CP_COMMIT() asm volatile("cp.async.commit_group;" ::: "memory")

__global__ __launch_bounds__(256, 1)
void mma_nt_kernel(const __nv_bfloat16* __restrict__ Ahi,
                   const __nv_bfloat16* __restrict__ Alo,
                   const __nv_bfloat16* __restrict__ Bhi,
                   const __nv_bfloat16* __restrict__ Blo,
                   size_t lda, float* __restrict__ Cbase, int ldc,
                   int K, float scale, int mode)
{
    extern __shared__ char dsm[];
    uint32_t sbase = smem_u32(dsm);

    int tid  = threadIdx.x;
    int wid  = tid >> 5;
    int lane = tid & 31;

    int t = blockIdx.x;
    int bi = (int)((sqrtf(8.f * (float)t + 1.f) - 1.f) * 0.5f);
    while ((bi + 1) * (bi + 2) / 2 <= t) bi++;
    while (bi * (bi + 1) / 2 > t) bi--;
    int bj = t - bi * (bi + 1) / 2;

    const __nv_bfloat16* srcs[4] = {
        Ahi + (size_t)bi * 128 * lda,
        Alo + (size_t)bi * 128 * lda,
        Bhi + (size_t)bj * 128 * lda,
        Blo + (size_t)bj * 128 * lda
    };

    int m0w = (wid & 1) * 64;
    int n0w = (wid >> 1) * 32;

    float acc[4][4][4];
#pragma unroll
    for (int im = 0; im < 4; im++)
#pragma unroll
        for (int jn = 0; jn < 4; jn++)
#pragma unroll
            for (int e = 0; e < 4; e++) acc[im][jn][e] = 0.f;

    const int S = K / BKG;

    {
#pragma unroll
        for (int it = 0; it < 8; it++) {
            int idx = tid + it * 256;
            int tile = idx >> 9;
            int rem = idx & 511;
            int r = rem >> 2, ch = rem & 3;
            uint32_t dst = sbase + (uint32_t)tile * GTILE_B + r * 80 + ch * 16;
            CP_ASYNC(dst, srcs[tile] + (size_t)r * lda + ch * 8);
        }
        CP_COMMIT();
    }

#pragma unroll 1
    for (int s = 0; s < S; s++) {
        if (s + 1 < S) {
            int k0 = (s + 1) * BKG;
            uint32_t boff = (uint32_t)((s + 1) & 1) * (4 * GTILE_B);
#pragma unroll
            for (int it = 0; it < 8; it++) {
                int idx = tid + it * 256;
                int tile = idx >> 9;
                int rem = idx & 511;
                int r = rem >> 2, ch = rem & 3;
                uint32_t dst = sbase + boff + (uint32_t)tile * GTILE_B +
                               r * 80 + ch * 16;
                CP_ASYNC(dst, srcs[tile] + (size_t)r * lda + k0 + ch * 8);
            }
            CP_COMMIT();
            asm volatile("cp.async.wait_group 1;" ::: "memory");
        } else {
            asm volatile("cp.async.wait_group 0;" ::: "memory");
        }
        __syncthreads();

        uint32_t buf = sbase + (uint32_t)(s & 1) * (4 * GTILE_B);
        uint32_t Ahi_b = buf;
        uint32_t Alo_b = buf + GTILE_B;
        uint32_t Bhi_b = buf + 2 * GTILE_B;
        uint32_t Blo_b = buf + 3 * GTILE_B;

#pragma unroll
        for (int ks = 0; ks < 2; ks++) {
            int kof = ks * 16;
            int arow = lane & 15;
            int acol = kof + 8 * (lane >> 4);
            uint32_t ah[4][4], al[4][4];
#pragma unroll
            for (int im = 0; im < 4; im++) {
                uint32_t ro = (uint32_t)(m0w + im * 16 + arow) * 80 + acol * 2;
                ldsm_x4(ah[im], Ahi_b + ro);
                if (mode == 1) ldsm_x4(al[im], Alo_b + ro);
            }
            int brow = lane & 7;
            int bcol = kof + 8 * ((lane >> 3) & 1);
            uint32_t bh[4][2], bl[4][2];
#pragma unroll
            for (int jn = 0; jn < 4; jn++) {
                uint32_t ro = (uint32_t)(n0w + jn * 8 + brow) * 80 + bcol * 2;
                ldsm_x2(bh[jn], Bhi_b + ro);
                ldsm_x2(bl[jn], Blo_b + ro);
            }
#pragma unroll
            for (int im = 0; im < 4; im++)
#pragma unroll
                for (int jn = 0; jn < 4; jn++) {
                    mma_bf16(acc[im][jn], ah[im], bh[jn]);
                    mma_bf16(acc[im][jn], ah[im], bl[jn]);
                    if (mode == 1) mma_bf16(acc[im][jn], al[im], bh[jn]);
                }
        }
        __syncthreads();
    }

#pragma unroll
    for (int im = 0; im < 4; im++) {
        int row = bi * 128 + m0w + im * 16 + (lane >> 2);
#pragma unroll
        for (int jn = 0; jn < 4; jn++) {
            int col = bj * 128 + n0w + jn * 8 + (lane & 3) * 2;
            float* p0 = Cbase + (size_t)row * ldc + col;
            float* p1 = Cbase + (size_t)(row + 8) * ldc + col;
            if (mode == 0) {
                p0[0] = fminf(fmaxf(acc[im][jn][0] * scale, -1.f), 1.f);
                p0[1] = fminf(fmaxf(acc[im][jn][1] * scale, -1.f), 1.f);
                p1[0] = fminf(fmaxf(acc[im][jn][2] * scale, -1.f), 1.f);
                p1[1] = fminf(fmaxf(acc[im][jn][3] * scale, -1.f), 1.f);
            } else {
                p0[0] -= acc[im][jn][0];
                p0[1] -= acc[im][jn][1];
                p1[0] -= acc[im][jn][2];
                p1[1] -= acc[im][jn][3];
            }
        }
    }
}

// ==========================================================================
__global__ void diag_kernel()
{
    int i = blockIdx.x * blockDim.x + threadIdx.x;
    if (i < N) g_diag[i] = g_S[(size_t)i * N + i];
}

__global__ void step_kernel(const float* __restrict__ alpha_p)
{
    int j = blockIdx.x * 32 + threadIdx.x;
    int i = blockIdx.y * 8 + threadIdx.y;
    if (i >= N || j > i) return;
    float a  = *alpha_p;
    float a2 = a * a;
    float cross = sqrtf(g_diag[i] * g_diag[j]);
    float s = g_S[(size_t)i * N + j];
    float m = fminf(fmaxf(s / cross, -1.f), 1.f);
    float q = 1.f - m * m;
    float sq, ac;
    if (q > 0.f) { sq = sqrtf(q); ac = acosf(m); }
    else         { sq = 0.f;      ac = (m > 0.f) ? 0.f : PI_F; }
    float f  = (sq + m * (PI_F - ac)) / PI_F;
    float ts = cross * f;
    float ov = (s + a2 * ts) / (1.f + a2);
    g_S[(size_t)i * N + j] = fminf(fmaxf(ov, -1.f), 1.f);
}

// ==========================================================================
// panel factorization + inversion of 128x128 diag block.
// ==========================================================================
__global__ __launch_bounds__(256, 1)
void potrf_invert(int kb)
{
    extern __shared__ float sh[];
    float* A = sh;                 // NB x NB stride LDA (L, lower)
    float* W = sh + NB * LDA;      // NB x NB stride LDA (inv(L), lower)
    __shared__ float Ts[3 * 1056];
    int tid = threadIdx.x;
    int base = kb * NB;

    for (int idx = tid; idx < NB * 32; idx += 256) {
        int i = idx >> 5, j4 = (idx & 31) << 2;
        float4 v = *(const float4*)&g_S[(size_t)(base + i) * N + base + j4];
        A[i * LDA + j4 + 0] = v.x;
        A[i * LDA + j4 + 1] = v.y;
        A[i * LDA + j4 + 2] = v.z;
        A[i * LDA + j4 + 3] = v.w;
    }
    __syncthreads();

    for (int p = 0; p < 4; p++) {
        int off = p * 32;

        if (tid < 32) {
            const unsigned FULL = 0xffffffffu;
            int r = tid;
            float ar[32];
#pragma unroll
            for (int t = 0; t < 32; t++)
                ar[t] = (t <= r) ? A[(off + r) * LDA + off + t] : 0.f;
            float rs_reg = 0.f;
#pragma unroll
            for (int j = 0; j < 32; j++) {
                float d   = __shfl_sync(FULL, ar[j], j);
                float rsj = rsqrtf(d);
                float lj  = ar[j] * rsj;
                ar[j] = lj;
                if (r == j) rs_reg = rsj;
#pragma unroll
                for (int t = j + 1; t < 32; t++) {
                    float ltj = __shfl_sync(FULL, lj, t);
                    ar[t] -= lj * ltj;
                }
            }
            int c = r;
            float w[32];
#pragma unroll
            for (int t = 0; t < 32; t++) w[t] = 0.f;
#pragma unroll
            for (int i = 0; i < 32; i++) {
                float s = (i == c) ? 1.f : 0.f;
#pragma unroll
                for (int t = 0; t < i; t++) {
                    float lit = __shfl_sync(FULL, ar[t], i);
                    s -= lit * w[t];
                }
                float rsi = __shfl_sync(FULL, rs_reg, i);
                w[i] = (i >= c) ? s * rsi : 0.f;
            }
#pragma unroll
            for (int t = 0; t < 32; t++)
                if (t <= r) A[(off + r) * LDA + off + t] = ar[t];
#pragma unroll
            for (int i = 0; i < 32; i++)
                W[(off + i) * LDA + off + c] = w[i];
        }
        __syncthreads();

        int nr = NB - off - 32;
        if (nr > 0) {
            int ntr = (nr >> 2) * 8;
            float acc[4][4];
            int tr = 0, tc = 0;
            if (tid < ntr) {
                tr = (tid >> 3) * 4;
                tc = (tid & 7) * 4;
#pragma unroll
                for (int r = 0; r < 4; r++)
#pragma unroll
                    for (int cidx = 0; cidx < 4; cidx++) acc[r][cidx] = 0.f;
#pragma unroll 8
                for (int k = 0; k < 32; k++) {
                    float av[4], wv[4];
#pragma unroll
                    for (int r = 0; r < 4; r++)
                        av[r] = A[(off + 32 + tr + r) * LDA + off + k];
#pragma unroll
                    for (int cidx = 0; cidx < 4; cidx++)
                        wv[cidx] = W[(off + tc + cidx) * LDA + off + k];
#pragma unroll
                    for (int r = 0; r < 4; r++)
#pragma unroll
                        for (int cidx = 0; cidx < 4; cidx++)
                            acc[r][cidx] += av[r] * wv[cidx];
                }
            }
            __syncthreads();
            if (tid < ntr) {
#pragma unroll
                for (int r = 0; r < 4; r++)
#pragma unroll
                    for (int cidx = 0; cidx < 4; cidx++)
                        A[(off + 32 + tr + r) * LDA + off + tc + cidx] =
                            acc[r][cidx];
            }
            __syncthreads();

            int nt = nr >> 2;
            int ntot = nt * (nt + 1) / 2;
            for (int tId = tid; tId < ntot; tId += 256) {
                int ti = (int)((sqrtf(8.f * (float)tId + 1.f) - 1.f) * 0.5f);
                while ((ti + 1) * (ti + 2) / 2 <= tId) ti++;
                while (ti * (ti + 1) / 2 > tId) ti--;
                int tj = tId - ti * (ti + 1) / 2;
                int i0 = off + 32 + ti * 4;
                int t0 = off + 32 + tj * 4;
                float a2[4][4];
#pragma unroll
                for (int r = 0; r < 4; r++)
#pragma unroll
                    for (int cidx = 0; cidx < 4; cidx++) a2[r][cidx] = 0.f;
#pragma unroll 8
                for (int k = 0; k < 32; k++) {
                    float av[4], bv[4];
#pragma unroll
                    for (int r = 0; r < 4; r++)
                        av[r] = A[(i0 + r) * LDA + off + k];
#pragma unroll
                    for (int cidx = 0; cidx < 4; cidx++)
                        bv[cidx] = A[(t0 + cidx) * LDA + off + k];
#pragma unroll
                    for (int r = 0; r < 4; r++)
#pragma unroll
                        for (int cidx = 0; cidx < 4; cidx++)
                            a2[r][cidx] += av[r] * bv[cidx];
                }
#pragma unroll
                for (int r = 0; r < 4; r++)
#pragma unroll
                    for (int cidx = 0; cidx < 4; cidx++) {
                        int ii = i0 + r, tt = t0 + cidx;
                        if (tt <= ii) A[ii * LDA + tt] -= a2[r][cidx];
                    }
            }
            __syncthreads();
        }
    }

    for (int ib = 1; ib < 4; ib++) {
        for (int tId = tid; tId < ib * 64; tId += 256) {
            int j = tId >> 6;
            int e = tId & 63;
            int r0 = (e >> 3) * 4, c0 = (e & 7) * 4;
            float acc[4][4];
#pragma unroll
            for (int r = 0; r < 4; r++)
#pragma unroll
                for (int cidx = 0; cidx < 4; cidx++) acc[r][cidx] = 0.f;
            for (int tb = j; tb < ib; tb++) {
#pragma unroll 8
                for (int k = 0; k < 32; k++) {
                    float lv[4], wv[4];
#pragma unroll
                    for (int r = 0; r < 4; r++)
                        lv[r] = A[(32 * ib + r0 + r) * LDA + 32 * tb + k];
#pragma unroll
                    for (int cidx = 0; cidx < 4; cidx++)
                        wv[cidx] = W[(32 * tb + k) * LDA + 32 * j + c0 + cidx];
#pragma unroll
                    for (int r = 0; r < 4; r++)
#pragma unroll
                        for (int cidx = 0; cidx < 4; cidx++)
                            acc[r][cidx] += lv[r] * wv[cidx];
                }
            }
#pragma unroll
            for (int r = 0; r < 4; r++)
#pragma unroll
                for (int cidx = 0; cidx < 4; cidx++)
                    Ts[j * 1056 + (r0 + r) * 33 + c0 + cidx] = acc[r][cidx];
        }
        __syncthreads();
        for (int tId = tid; tId < ib * 64; tId += 256) {
            int j = tId >> 6;
            int e = tId & 63;
            int r0 = (e >> 3) * 4, c0 = (e & 7) * 4;
            float acc[4][4];
#pragma unroll
            for (int r = 0; r < 4; r++)
#pragma unroll
                for (int cidx = 0; cidx < 4; cidx++) acc[r][cidx] = 0.f;
#pragma unroll 8
            for (int k = 0; k < 32; k++) {
                float wv[4], tv[4];
#pragma unroll
                for (int r = 0; r < 4; r++)
                    wv[r] = W[(32 * ib + r0 + r) * LDA + 32 * ib + k];
#pragma unroll
                for (int cidx = 0; cidx < 4; cidx++)
                    tv[cidx] = Ts[j * 1056 + k * 33 + c0 + cidx];
#pragma unroll
                for (int r = 0; r < 4; r++)
#pragma unroll
                    for (int cidx = 0; cidx < 4; cidx++)
                        acc[r][cidx] += wv[r] * tv[cidx];
            }
#pragma unroll
            for (int r = 0; r < 4; r++)
#pragma unroll
                for (int cidx = 0; cidx < 4; cidx++)
                    W[(32 * ib + r0 + r) * LDA + 32 * j + c0 + cidx] =
                        -acc[r][cidx];
        }
        __syncthreads();
    }

    for (int idx = tid; idx < NB * NB; idx += 256) {
        int i = idx >> 7, j = idx & 127;
        if (j <= i) g_S[(size_t)(base + i) * N + base + j] = A[i * LDA + j];
        g_invD[(size_t)kb * NB * NB + idx] =
            ((j >> 5) <= (i >> 5)) ? W[i * LDA + j] : 0.f;
    }
}

// ==========================================================================
// TRSM panel GEMM: C = A * B^T (64x64 tiles); writes fp32 L into S and
// bf16 hi/lo split panels for the mma SYRK.
// ==========================================================================
__global__ __launch_bounds__(256, 2)
void gemm_nt_split(const float* __restrict__ A, int lda,
                   const float* __restrict__ B, int ldb,
                   float* __restrict__ Cs, int ldcs,
                   __nv_bfloat16* __restrict__ Phi,
                   __nv_bfloat16* __restrict__ Plo, int K)
{
    __shared__ float As[16][64];
    __shared__ float Bs[16][64];
    int bi = blockIdx.y, bj = blockIdx.x;
    int tid = threadIdx.x;
    int tx = tid & 15, ty = tid >> 4;

    const float* Ab = A + (size_t)(bi * 64) * lda;
    const float* Bb = B + (size_t)(bj * 64) * ldb;

    int arow = tid >> 2, akk = (tid & 3) << 2;

    float acc[4][4];
#pragma unroll
    for (int i = 0; i < 4; i++)
#pragma unroll
        for (int j = 0; j < 4; j++) acc[i][j] = 0.f;

    for (int k0 = 0; k0 < K; k0 += 16) {
        float4 va = *(const float4*)(Ab + (size_t)arow * lda + k0 + akk);
        float4 vb = *(const float4*)(Bb + (size_t)arow * ldb + k0 + akk);
        As[akk + 0][arow] = va.x; As[akk + 1][arow] = va.y;
        As[akk + 2][arow] = va.z; As[akk + 3][arow] = va.w;
        Bs[akk + 0][arow] = vb.x; Bs[akk + 1][arow] = vb.y;
        Bs[akk + 2][arow] = vb.z; Bs[akk + 3][arow] = vb.w;
        __syncthreads();
#pragma unroll
        for (int kk = 0; kk < 16; kk++) {
            float4 a = *(const float4*)&As[kk][ty * 4];
            float4 b = *(const float4*)&Bs[kk][tx * 4];
            float av[4] = {a.x, a.y, a.z, a.w};
            float bv[4] = {b.x, b.y, b.z, b.w};
#pragma unroll
            for (int i = 0; i < 4; i++)
#pragma unroll
                for (int j = 0; j < 4; j++)
                    acc[i][j] += av[i] * bv[j];
        }
        __syncthreads();
    }

#pragma unroll
    for (int i = 0; i < 4; i++) {
        int row = bi * 64 + ty * 4 + i;
#pragma unroll
        for (int j = 0; j < 4; j++) {
            int col = bj * 64 + tx * 4 + j;
            float v = acc[i][j];
            Cs[(size_t)row * ldcs + col] = v;
            __nv_bfloat16 h = __float2bfloat16(v);
            Phi[(size_t)row * NB + col] = h;
            Plo[(size_t)row * NB + col] =
                __float2bfloat16(v - __bfloat162float(h));
        }
    }
}

// ==========================================================================
// batched NN GEMM, 128x128 tiles / 8x8 micro-tiles (for D&C inversion)
// ==========================================================================
__global__ __launch_bounds__(256, 1)
void gemm_nn_b128(const float* __restrict__ A, size_t strA, int lda,
                  const float* __restrict__ B, size_t strB, int ldb,
                  float* __restrict__ C, size_t strC, int ldc,
                  int K, float alpha)
{
    A += (size_t)blockIdx.z * strA;
    B += (size_t)blockIdx.z * strB;
    C += (size_t)blockIdx.z * strC;

    __shared__ float As[8][128];
    __shared__ float Bs[8][128];

    int bi = blockIdx.y, bj = blockIdx.x;
    int tid = threadIdx.x;
    int tx = tid & 15, ty = tid >> 4;

    int lrow = tid >> 1;
    int lkk  = (tid & 1) * 4;
    int brow = tid >> 5;
    int bcol = (tid & 31) * 4;

    const float* Ap = A + (size_t)(bi * 128 + lrow) * lda + lkk;
    const float* Bp = B + bj * 128 + bcol;

    float acc[8][8];
#pragma unroll
    for (int i = 0; i < 8; i++)
#pragma unroll
        for (int j = 0; j < 8; j++) acc[i][j] = 0.f;

    for (int k0 = 0; k0 < K; k0 += 8) {
        float4 va = *(const float4*)(Ap + k0);
        float4 vb = *(const float4*)(Bp + (size_t)(k0 + brow) * ldb);
        if (k0) __syncthreads();
        As[lkk + 0][lrow] = va.x; As[lkk + 1][lrow] = va.y;
        As[lkk + 2][lrow] = va.z; As[lkk + 3][lrow] = va.w;
        *(float4*)&Bs[brow][bcol] = vb;
        __syncthreads();
#pragma unroll
        for (int kk = 0; kk < 8; kk++) {
            float4 a0 = *(const float4*)&As[kk][ty * 4];
            float4 a1 = *(const float4*)&As[kk][64 + ty * 4];
            float4 b0 = *(const float4*)&Bs[kk][tx * 4];
            float4 b1 = *(const float4*)&Bs[kk][64 + tx * 4];
            float a[8] = {a0.x, a0.y, a0.z, a0.w, a1.x, a1.y, a1.z, a1.w};
            float b[8] = {b0.x, b0.y, b0.z, b0.w, b1.x, b1.y, b1.z, b1.w};
#pragma unroll
            for (int i = 0; i < 8; i++)
#pragma unroll
                for (int j = 0; j < 8; j++)
                    acc[i][j] += a[i] * b[j];
        }
    }

#pragma unroll
    for (int i = 0; i < 8; i++) {
        int r = bi * 128 + ((i < 4) ? ty * 4 + i : 64 + ty * 4 + (i - 4));
#pragma unroll
        for (int j = 0; j < 8; j++) {
            int cc = bj * 128 + ((j < 4) ? tx * 4 + j : 64 + tx * 4 + (j - 4));
            C[(size_t)r * ldc + cc] = alpha * acc[i][j];
        }
    }
}

// ==========================================================================
__global__ void zero_kernel(float* p, int n)
{
    for (int i = blockIdx.x * blockDim.x + threadIdx.x; i < n;
         i += gridDim.x * blockDim.x)
        p[i] = 0.f;
}

__global__ void copy_diag_kernel()
{
    int kb = blockIdx.y;
    int idx = blockIdx.x * 256 + threadIdx.x;
    int i = idx >> 7, j = idx & 127;
    g_W[(size_t)(kb * NB + i) * N + kb * NB + j] =
        g_invD[(size_t)kb * NB * NB + idx];
}

__global__ void fnorm_kernel()
{
    __shared__ float red[256];
    float s = 0.f;
    size_t total = (size_t)N * N;
    for (size_t i = blockIdx.x * blockDim.x + threadIdx.x; i < total;
         i += (size_t)gridDim.x * blockDim.x) {
        float v = g_W[i];
        s += v * v;
    }
    red[threadIdx.x] = s; __syncthreads();
    for (int o = 128; o > 0; o >>= 1) {
        if (threadIdx.x < o) red[threadIdx.x] += red[threadIdx.x + o];
        __syncthreads();
    }
    if (threadIdx.x == 0) atomicAdd(&g_scal[0], red[0]);
}

__global__ void proj_kernel(const float* __restrict__ c)
{
    __shared__ float red[256];
    int r = blockIdx.x;
    const float* row = g_W + (size_t)r * N;
    float s = 0.f;
    for (int j = threadIdx.x; j < N; j += 256) s += row[j] * c[j];
    red[threadIdx.x] = s; __syncthreads();
    for (int o = 128; o > 0; o >>= 1) {
        if (threadIdx.x < o) red[threadIdx.x] += red[threadIdx.x + o];
        __syncthreads();
    }
    if (threadIdx.x == 0) {
        float y = red[0];
        atomicAdd(&g_scal[1], y * y);
    }
}

__global__ void final_kernel(float* out)
{
    __shared__ float red[256];
    float s = 0.f;
    for (int i = threadIdx.x; i < N; i += 256)
        s += logf(g_S[(size_t)i * N + i]);
    red[threadIdx.x] = s; __syncthreads();
    for (int o = 128; o > 0; o >>= 1) {
        if (threadIdx.x < o) red[threadIdx.x] += red[threadIdx.x + o];
        __syncthreads();
    }
    if (threadIdx.x == 0) {
        float nrd = expf(red[0] * (2.0f / (float)N));
        out[0] = (float)N / 5.0f +
                 nrd * ((0.5f - 1.0f / PI_F) * g_scal[0] + g_scal[1] / PI_F);
    }
}

// ==========================================================================
// host orchestration
// ==========================================================================
extern "C" void kernel_launch(void* const* d_in, const int* in_sizes, int n_in,
                              void* d_out, int out_size)
{
    (void)in_sizes; (void)n_in; (void)out_size;
    const float* x     = (const float*)d_in[0];
    const float* c     = (const float*)d_in[1];
    const float* alpha = (const float*)d_in[2];
    float* out = (float*)d_out;

    float *Sp, *Wp, *iDp, *T2p, *scalp;
    __nv_bfloat16 *hip, *lop, *Phip, *Plop;
    cudaGetSymbolAddress((void**)&Sp,    g_S);
    cudaGetSymbolAddress((void**)&Wp,    g_W);
    cudaGetSymbolAddress((void**)&iDp,   g_invD);
    cudaGetSymbolAddress((void**)&T2p,   g_T2);
    cudaGetSymbolAddress((void**)&scalp, g_scal);
    cudaGetSymbolAddress((void**)&hip,   g_hi);
    cudaGetSymbolAddress((void**)&lop,   g_lo);
    cudaGetSymbolAddress((void**)&Phip,  g_Phi);
    cudaGetSymbolAddress((void**)&Plop,  g_Plo);

    int potrf_smem = 2 * NB * LDA * (int)sizeof(float);
    cudaFuncSetAttribute(potrf_invert,
                         cudaFuncAttributeMaxDynamicSharedMemorySize,
                         potrf_smem);
    cudaFuncSetAttribute(mma_nt_kernel,
                         cudaFuncAttributeMaxDynamicSharedMemorySize,
                         GRAM_SMEM);

    // 1. gram via bf16 split mma (2 products: hi*hi + hi*lo)
    split_kernel<<<4096, 256>>>(x);
    mma_nt_kernel<<<NBLK * (NBLK + 1) / 2, 256, GRAM_SMEM>>>(
        hip, lop, hip, lop, D, Sp, N, D, 1.0f / (float)D, 0);

    // 2. arc-cosine kernel step
    diag_kernel<<<N / 256, 256>>>();
    step_kernel<<<dim3(N / 32, N / 8), dim3(32, 8)>>>(alpha);

    // 3. blocked Cholesky (in place, lower)
    for (int k = 0; k < NBLK; k++) {
        potrf_invert<<<1, 256, potrf_smem>>>(k);
        if (k < NBLK - 1) {
            int rows = (NBLK - 1 - k) * NB;
            gemm_nt_split<<<dim3(2, rows / 64), 256>>>(
                Sp + (size_t)(k + 1) * NB * N + (size_t)k * NB, N,
                iDp + (size_t)k * NB * NB, NB,
                Sp + (size_t)(k + 1) * NB * N + (size_t)k * NB, N,
                Phip, Plop, NB);
            int T2 = NBLK - 1 - k;
            mma_nt_kernel<<<T2 * (T2 + 1) / 2, 256, GRAM_SMEM>>>(
                Phip, Plop, Phip, Plop, NB,
                Sp + (size_t)(k + 1) * NB * N + (size_t)(k + 1) * NB, N,
                NB, 1.0f, 1);
        }
    }

    // 4. divide & conquer triangular inversion: W = L^{-1}
    zero_kernel<<<4096, 256>>>(Wp, N * N);
    copy_diag_kernel<<<dim3(64, NBLK), 256>>>();
    for (int lev = 0; lev < 4; lev++) {
        int s = 128 << lev;
        int pairs = N / (2 * s);
        size_t strW = (size_t)2 * s * (N + 1);
        gemm_nn_b128<<<dim3(s / 128, s / 128, pairs), 256>>>(
            Wp + (size_t)s * N + s, strW, N,
            Sp + (size_t)s * N,     strW, N,
            T2p, (size_t)s * s, s,
            s, 1.0f);
        gemm_nn_b128<<<dim3(s / 128, s / 128, pairs), 256>>>(
            T2p, (size_t)s * s, s,
            Wp, strW, N,
            Wp + (size_t)s * N, strW, N,
            s, -1.0f);
    }

    // 5. reductions + final scalar
    zero_kernel<<<1, 32>>>(scalp, 4);
    fnorm_kernel<<<1024, 256>>>();
    proj_kernel<<<N, 256>>>(c);
    final_kernel<<<1, 256>>>(out);
}

// round 12
// speedup vs baseline: 1.5515x; 1.1243x over previous
#include <cuda_runtime.h>
#include <cuda_bf16.h>
#include <math.h>
#include <stdint.h>

#define N 2048
#define D 16384
#define NB 128
#define LDA 129            // padded smem stride (bank-conflict-free columns)
#define NBLK 16            // N / NB
#define PI_F 3.14159265358979323846f

// ---------------- device scratch (no allocations allowed) ----------------
__device__ float g_S[(size_t)N * N];        // gram / sigma / L (lower, in place)
__device__ float g_W[(size_t)N * N];        // L^{-1} (lower)
__device__ float g_invD[NBLK * NB * NB];    // per-panel inv(L11)
__device__ float g_T2[(size_t)1024 * 1024]; // D&C inversion scratch
__device__ float g_diag[N];                 // diag snapshot
__device__ float g_scal[4];                 // [0]=trace acc, [1]=proj acc
__device__ __nv_bfloat16 g_hi[(size_t)N * D];
__device__ __nv_bfloat16 g_lo[(size_t)N * D];
__device__ __nv_bfloat16 g_Phi[(size_t)N * NB];  // TRSM panel, bf16 hi
__device__ __nv_bfloat16 g_Plo[(size_t)N * NB];  // TRSM panel, bf16 lo

// ==========================================================================
__device__ __forceinline__ uint32_t smem_u32(const void* p) {
    uint32_t a;
    asm("{ .reg .u64 t; cvta.to.shared.u64 t, %1; cvt.u32.u64 %0, t; }"
        : "=r"(a) : "l"(p));
    return a;
}

// ==========================================================================
// split conversion: x -> hi (bf16) + lo (bf16 of residual), vectorized
// ==========================================================================
__global__ void split_kernel(const float* __restrict__ x)
{
    size_t total = (size_t)N * D / 4;
    const float4* x4 = (const float4*)x;
    for (size_t i = blockIdx.x * (size_t)blockDim.x + threadIdx.x; i < total;
         i += (size_t)gridDim.x * blockDim.x) {
        float4 v = x4[i];
        __nv_bfloat16 h0 = __float2bfloat16(v.x);
        __nv_bfloat16 h1 = __float2bfloat16(v.y);
        __nv_bfloat16 h2 = __float2bfloat16(v.z);
        __nv_bfloat16 h3 = __float2bfloat16(v.w);
        __nv_bfloat162* hp = (__nv_bfloat162*)(g_hi + i * 4);
        __nv_bfloat162* lp = (__nv_bfloat162*)(g_lo + i * 4);
        hp[0] = __nv_bfloat162(h0, h1);
        hp[1] = __nv_bfloat162(h2, h3);
        lp[0] = __nv_bfloat162(__float2bfloat16(v.x - __bfloat162float(h0)),
                               __float2bfloat16(v.y - __bfloat162float(h1)));
        lp[1] = __nv_bfloat162(__float2bfloat16(v.z - __bfloat162float(h2)),
                               __float2bfloat16(v.w - __bfloat162float(h3)));
    }
}

// ==========================================================================
// templated bf16-split NT mma kernel over lower tile pairs:
// NPROD=2: acc = Ahi*Bhi^T + Ahi*Blo^T         (gram; Alo tile not loaded)
// NPROD=3: acc += Alo*Bhi^T as well            (SYRK)
// MODE=0:  C = clip(acc*scale, -1, 1)
// MODE=1:  C -= acc
// ==========================================================================
#define BKG 32
#define GTILE_B (128 * 40 * 2)
#define GRAM_SMEM (2 * 4 * GTILE_B)

__device__ __forceinline__ void ldsm_x4(uint32_t* r, uint32_t addr) {
    asm volatile("ldmatrix.sync.aligned.m8n8.x4.shared.b16 {%0,%1,%2,%3}, [%4];"
                 : "=r"(r[0]), "=r"(r[1]), "=r"(r[2]), "=r"(r[3]) : "r"(addr));
}
__device__ __forceinline__ void ldsm_x2(uint32_t* r, uint32_t addr) {
    asm volatile("ldmatrix.sync.aligned.m8n8.x2.shared.b16 {%0,%1}, [%2];"
                 : "=r"(r[0]), "=r"(r[1]) : "r"(addr));
}
__device__ __forceinline__ void mma_bf16(float* d, const uint32_t* a,
                                         const uint32_t* b) {
    asm volatile(
        "mma.sync.aligned.m16n8k16.row.col.f32.bf16.bf16.f32 "
        "{%0,%1,%2,%3}, {%4,%5,%6,%7}, {%8,%9}, {%0,%1,%2,%3};"
        : "+f"(d[0]), "+f"(d[1]), "+f"(d[2]), "+f"(d[3])
        : "r"(a[0]), "r"(a[1]), "r"(a[2]), "r"(a[3]), "r"(b[0]), "r"(b[1]));
}
#define CP_ASYNC(dst, src) \
    asm volatile("cp.async.cg.shared.global [%0], [%1], 16;" \
                 :: "r"(dst), "l"(src))
#define CP_COMMIT() asm volatile("cp.async.commit_group;" ::: "memory")

template <int NPROD, int MODE>
__global__ __launch_bounds__(256, 1)
void mma_nt_kernel(const __nv_bfloat16* __restrict__ Ahi,
                   const __nv_bfloat16* __restrict__ Alo,
                   const __nv_bfloat16* __restrict__ Bhi,
                   const __nv_bfloat16* __restrict__ Blo,
                   size_t lda, float* __restrict__ Cbase, int ldc,
                   int K, float scale)
{
    extern __shared__ char dsm[];
    uint32_t sbase = smem_u32(dsm);

    int tid  = threadIdx.x;
    int wid  = tid >> 5;
    int lane = tid & 31;

    int t = blockIdx.x;
    int bi = (int)((sqrtf(8.f * (float)t + 1.f) - 1.f) * 0.5f);
    while ((bi + 1) * (bi + 2) / 2 <= t) bi++;
    while (bi * (bi + 1) / 2 > t) bi--;
    int bj = t - bi * (bi + 1) / 2;

    const __nv_bfloat16* srcs[4] = {
        Ahi + (size_t)bi * 128 * lda,
        Alo + (size_t)bi * 128 * lda,
        Bhi + (size_t)bj * 128 * lda,
        Blo + (size_t)bj * 128 * lda
    };

    int m0w = (wid & 1) * 64;
    int n0w = (wid >> 1) * 32;

    float acc[4][4][4];
#pragma unroll
    for (int im = 0; im < 4; im++)
#pragma unroll
        for (int jn = 0; jn < 4; jn++)
#pragma unroll
            for (int e = 0; e < 4; e++) acc[im][jn][e] = 0.f;

    const int S = K / BKG;

    {
#pragma unroll
        for (int it = 0; it < 8; it++) {
            int idx = tid + it * 256;
            int tile = idx >> 9;
            int rem = idx & 511;
            int r = rem >> 2, ch = rem & 3;
            if (NPROD == 2 && tile == 1) continue;   // Alo unused in gram
            uint32_t dst = sbase + (uint32_t)tile * GTILE_B + r * 80 + ch * 16;
            CP_ASYNC(dst, srcs[tile] + (size_t)r * lda + ch * 8);
        }
        CP_COMMIT();
    }

#pragma unroll 1
    for (int s = 0; s < S; s++) {
        if (s + 1 < S) {
            int k0 = (s + 1) * BKG;
            uint32_t boff = (uint32_t)((s + 1) & 1) * (4 * GTILE_B);
#pragma unroll
            for (int it = 0; it < 8; it++) {
                int idx = tid + it * 256;
                int tile = idx >> 9;
                int rem = idx & 511;
                int r = rem >> 2, ch = rem & 3;
                if (NPROD == 2 && tile == 1) continue;
                uint32_t dst = sbase + boff + (uint32_t)tile * GTILE_B +
                               r * 80 + ch * 16;
                CP_ASYNC(dst, srcs[tile] + (size_t)r * lda + k0 + ch * 8);
            }
            CP_COMMIT();
            asm volatile("cp.async.wait_group 1;" ::: "memory");
        } else {
            asm volatile("cp.async.wait_group 0;" ::: "memory");
        }
        __syncthreads();

        uint32_t buf = sbase + (uint32_t)(s & 1) * (4 * GTILE_B);
        uint32_t Ahi_b = buf;
        uint32_t Alo_b = buf + GTILE_B;
        uint32_t Bhi_b = buf + 2 * GTILE_B;
        uint32_t Blo_b = buf + 3 * GTILE_B;

#pragma unroll
        for (int ks = 0; ks < 2; ks++) {
            int kof = ks * 16;
            int arow = lane & 15;
            int acol = kof + 8 * (lane >> 4);
            uint32_t ah[4][4], al[4][4];
#pragma unroll
            for (int im = 0; im < 4; im++) {
                uint32_t ro = (uint32_t)(m0w + im * 16 + arow) * 80 + acol * 2;
                ldsm_x4(ah[im], Ahi_b + ro);
                if (NPROD == 3) ldsm_x4(al[im], Alo_b + ro);
            }
            int brow = lane & 7;
            int bcol = kof + 8 * ((lane >> 3) & 1);
            uint32_t bh[4][2], bl[4][2];
#pragma unroll
            for (int jn = 0; jn < 4; jn++) {
                uint32_t ro = (uint32_t)(n0w + jn * 8 + brow) * 80 + bcol * 2;
                ldsm_x2(bh[jn], Bhi_b + ro);
                ldsm_x2(bl[jn], Blo_b + ro);
            }
#pragma unroll
            for (int im = 0; im < 4; im++)
#pragma unroll
                for (int jn = 0; jn < 4; jn++) {
                    mma_bf16(acc[im][jn], ah[im], bh[jn]);
                    mma_bf16(acc[im][jn], ah[im], bl[jn]);
                    if (NPROD == 3) mma_bf16(acc[im][jn], al[im], bh[jn]);
                }
        }
        __syncthreads();
    }

#pragma unroll
    for (int im = 0; im < 4; im++) {
        int row = bi * 128 + m0w + im * 16 + (lane >> 2);
#pragma unroll
        for (int jn = 0; jn < 4; jn++) {
            int col = bj * 128 + n0w + jn * 8 + (lane & 3) * 2;
            float* p0 = Cbase + (size_t)row * ldc + col;
            float* p1 = Cbase + (size_t)(row + 8) * ldc + col;
            if (MODE == 0) {
                p0[0] = fminf(fmaxf(acc[im][jn][0] * scale, -1.f), 1.f);
                p0[1] = fminf(fmaxf(acc[im][jn][1] * scale, -1.f), 1.f);
                p1[0] = fminf(fmaxf(acc[im][jn][2] * scale, -1.f), 1.f);
                p1[1] = fminf(fmaxf(acc[im][jn][3] * scale, -1.f), 1.f);
            } else {
                p0[0] -= acc[im][jn][0];
                p0[1] -= acc[im][jn][1];
                p1[0] -= acc[im][jn][2];
                p1[1] -= acc[im][jn][3];
            }
        }
    }
}

// ==========================================================================
__global__ void diag_kernel()
{
    int i = blockIdx.x * blockDim.x + threadIdx.x;
    if (i < N) g_diag[i] = g_S[(size_t)i * N + i];
}

__global__ void step_kernel(const float* __restrict__ alpha_p)
{
    int j = blockIdx.x * 32 + threadIdx.x;
    int i = blockIdx.y * 8 + threadIdx.y;
    if (i >= N || j > i) return;
    float a  = *alpha_p;
    float a2 = a * a;
    float cross = sqrtf(g_diag[i] * g_diag[j]);
    float s = g_S[(size_t)i * N + j];
    float m = fminf(fmaxf(s / cross, -1.f), 1.f);
    float q = 1.f - m * m;
    float sq, ac;
    if (q > 0.f) { sq = sqrtf(q); ac = acosf(m); }
    else         { sq = 0.f;      ac = (m > 0.f) ? 0.f : PI_F; }
    float f  = (sq + m * (PI_F - ac)) / PI_F;
    float ts = cross * f;
    float ov = (s + a2 * ts) / (1.f + a2);
    g_S[(size_t)i * N + j] = fminf(fmaxf(ov, -1.f), 1.f);
}

// ==========================================================================
// panel factorization + inversion of 128x128 diag block (512 threads:
// all data-parallel phases single-pass).
// ==========================================================================
#define PT 512
__global__ __launch_bounds__(PT, 1)
void potrf_invert(int kb)
{
    extern __shared__ float sh[];
    float* A = sh;                 // NB x NB stride LDA (L, lower)
    float* W = sh + NB * LDA;      // NB x NB stride LDA (inv(L), lower)
    __shared__ float Ts[3 * 1056];
    int tid = threadIdx.x;
    int base = kb * NB;

    for (int idx = tid; idx < NB * 32; idx += PT) {
        int i = idx >> 5, j4 = (idx & 31) << 2;
        float4 v = *(const float4*)&g_S[(size_t)(base + i) * N + base + j4];
        A[i * LDA + j4 + 0] = v.x;
        A[i * LDA + j4 + 1] = v.y;
        A[i * LDA + j4 + 2] = v.z;
        A[i * LDA + j4 + 3] = v.w;
    }
    __syncthreads();

    for (int p = 0; p < 4; p++) {
        int off = p * 32;

        if (tid < 32) {
            const unsigned FULL = 0xffffffffu;
            int r = tid;
            float ar[32];
#pragma unroll
            for (int t = 0; t < 32; t++)
                ar[t] = (t <= r) ? A[(off + r) * LDA + off + t] : 0.f;
            float rs_reg = 0.f;
#pragma unroll
            for (int j = 0; j < 32; j++) {
                float d   = __shfl_sync(FULL, ar[j], j);
                float rsj = rsqrtf(d);
                float lj  = ar[j] * rsj;
                ar[j] = lj;
                if (r == j) rs_reg = rsj;
#pragma unroll
                for (int t = j + 1; t < 32; t++) {
                    float ltj = __shfl_sync(FULL, lj, t);
                    ar[t] -= lj * ltj;
                }
            }
            int c = r;
            float w[32];
#pragma unroll
            for (int t = 0; t < 32; t++) w[t] = 0.f;
#pragma unroll
            for (int i = 0; i < 32; i++) {
                float s = (i == c) ? 1.f : 0.f;
#pragma unroll
                for (int t = 0; t < i; t++) {
                    float lit = __shfl_sync(FULL, ar[t], i);
                    s -= lit * w[t];
                }
                float rsi = __shfl_sync(FULL, rs_reg, i);
                w[i] = (i >= c) ? s * rsi : 0.f;
            }
#pragma unroll
            for (int t = 0; t < 32; t++)
                if (t <= r) A[(off + r) * LDA + off + t] = ar[t];
#pragma unroll
            for (int i = 0; i < 32; i++)
                W[(off + i) * LDA + off + c] = w[i];
        }
        __syncthreads();

        int nr = NB - off - 32;
        if (nr > 0) {
            // ---- TRSM: 4x4 tiles, reg-staged, single pass (<=192 thr) ----
            int ntr = (nr >> 2) * 8;
            float acc[4][4];
            int tr = 0, tc = 0;
            if (tid < ntr) {
                tr = (tid >> 3) * 4;
                tc = (tid & 7) * 4;
#pragma unroll
                for (int r = 0; r < 4; r++)
#pragma unroll
                    for (int cidx = 0; cidx < 4; cidx++) acc[r][cidx] = 0.f;
#pragma unroll 8
                for (int k = 0; k < 32; k++) {
                    float av[4], wv[4];
#pragma unroll
                    for (int r = 0; r < 4; r++)
                        av[r] = A[(off + 32 + tr + r) * LDA + off + k];
#pragma unroll
                    for (int cidx = 0; cidx < 4; cidx++)
                        wv[cidx] = W[(off + tc + cidx) * LDA + off + k];
#pragma unroll
                    for (int r = 0; r < 4; r++)
#pragma unroll
                        for (int cidx = 0; cidx < 4; cidx++)
                            acc[r][cidx] += av[r] * wv[cidx];
                }
            }
            __syncthreads();
            if (tid < ntr) {
#pragma unroll
                for (int r = 0; r < 4; r++)
#pragma unroll
                    for (int cidx = 0; cidx < 4; cidx++)
                        A[(off + 32 + tr + r) * LDA + off + tc + cidx] =
                            acc[r][cidx];
            }
            __syncthreads();

            // ---- SYRK: 4x4 tiles, lower only, single pass (<=300 thr) ----
            int nt = nr >> 2;
            int ntot = nt * (nt + 1) / 2;
            for (int tId = tid; tId < ntot; tId += PT) {
                int ti = (int)((sqrtf(8.f * (float)tId + 1.f) - 1.f) * 0.5f);
                while ((ti + 1) * (ti + 2) / 2 <= tId) ti++;
                while (ti * (ti + 1) / 2 > tId) ti--;
                int tj = tId - ti * (ti + 1) / 2;
                int i0 = off + 32 + ti * 4;
                int t0 = off + 32 + tj * 4;
                float a2[4][4];
#pragma unroll
                for (int r = 0; r < 4; r++)
#pragma unroll
                    for (int cidx = 0; cidx < 4; cidx++) a2[r][cidx] = 0.f;
#pragma unroll 8
                for (int k = 0; k < 32; k++) {
                    float av[4], bv[4];
#pragma unroll
                    for (int r = 0; r < 4; r++)
                        av[r] = A[(i0 + r) * LDA + off + k];
#pragma unroll
                    for (int cidx = 0; cidx < 4; cidx++)
                        bv[cidx] = A[(t0 + cidx) * LDA + off + k];
#pragma unroll
                    for (int r = 0; r < 4; r++)
#pragma unroll
                        for (int cidx = 0; cidx < 4; cidx++)
                            a2[r][cidx] += av[r] * bv[cidx];
                }
#pragma unroll
                for (int r = 0; r < 4; r++)
#pragma unroll
                    for (int cidx = 0; cidx < 4; cidx++) {
                        int ii = i0 + r, tt = t0 + cidx;
                        if (tt <= ii) A[ii * LDA + tt] -= a2[r][cidx];
                    }
            }
            __syncthreads();
        }
    }

    // ---- blocked inversion of off-diag 32x32 blocks of W, 4x4 tiles ----
    for (int ib = 1; ib < 4; ib++) {
        for (int tId = tid; tId < ib * 64; tId += PT) {
            int j = tId >> 6;
            int e = tId & 63;
            int r0 = (e >> 3) * 4, c0 = (e & 7) * 4;
            float acc[4][4];
#pragma unroll
            for (int r = 0; r < 4; r++)
#pragma unroll
                for (int cidx = 0; cidx < 4; cidx++) acc[r][cidx] = 0.f;
            for (int tb = j; tb < ib; tb++) {
#pragma unroll 8
                for (int k = 0; k < 32; k++) {
                    float lv[4], wv[4];
#pragma unroll
                    for (int r = 0; r < 4; r++)
                        lv[r] = A[(32 * ib + r0 + r) * LDA + 32 * tb + k];
#pragma unroll
                    for (int cidx = 0; cidx < 4; cidx++)
                        wv[cidx] = W[(32 * tb + k) * LDA + 32 * j + c0 + cidx];
#pragma unroll
                    for (int r = 0; r < 4; r++)
#pragma unroll
                        for (int cidx = 0; cidx < 4; cidx++)
                            acc[r][cidx] += lv[r] * wv[cidx];
                }
            }
#pragma unroll
            for (int r = 0; r < 4; r++)
#pragma unroll
                for (int cidx = 0; cidx < 4; cidx++)
                    Ts[j * 1056 + (r0 + r) * 33 + c0 + cidx] = acc[r][cidx];
        }
        __syncthreads();
        for (int tId = tid; tId < ib * 64; tId += PT) {
            int j = tId >> 6;
            int e = tId & 63;
            int r0 = (e >> 3) * 4, c0 = (e & 7) * 4;
            float acc[4][4];
#pragma unroll
            for (int r = 0; r < 4; r++)
#pragma unroll
                for (int cidx = 0; cidx < 4; cidx++) acc[r][cidx] = 0.f;
#pragma unroll 8
            for (int k = 0; k < 32; k++) {
                float wv[4], tv[4];
#pragma unroll
                for (int r = 0; r < 4; r++)
                    wv[r] = W[(32 * ib + r0 + r) * LDA + 32 * ib + k];
#pragma unroll
                for (int cidx = 0; cidx < 4; cidx++)
                    tv[cidx] = Ts[j * 1056 + k * 33 + c0 + cidx];
#pragma unroll
                for (int r = 0; r < 4; r++)
#pragma unroll
                    for (int cidx = 0; cidx < 4; cidx++)
                        acc[r][cidx] += wv[r] * tv[cidx];
            }
#pragma unroll
            for (int r = 0; r < 4; r++)
#pragma unroll
                for (int cidx = 0; cidx < 4; cidx++)
                    W[(32 * ib + r0 + r) * LDA + 32 * j + c0 + cidx] =
                        -acc[r][cidx];
        }
        __syncthreads();
    }

    for (int idx = tid; idx < NB * NB; idx += PT) {
        int i = idx >> 7, j = idx & 127;
        if (j <= i) g_S[(size_t)(base + i) * N + base + j] = A[i * LDA + j];
        g_invD[(size_t)kb * NB * NB + idx] =
            ((j >> 5) <= (i >> 5)) ? W[i * LDA + j] : 0.f;
    }
}

// ==========================================================================
// TRSM panel GEMM: C = A * B^T (64x64 tiles); writes fp32 L into S and
// bf16 hi/lo split panels for the mma SYRK.
// ==========================================================================
__global__ __launch_bounds__(256, 2)
void gemm_nt_split(const float* __restrict__ A, int lda,
                   const float* __restrict__ B, int ldb,
                   float* __restrict__ Cs, int ldcs,
                   __nv_bfloat16* __restrict__ Phi,
                   __nv_bfloat16* __restrict__ Plo, int K)
{
    __shared__ float As[16][64];
    __shared__ float Bs[16][64];
    int bi = blockIdx.y, bj = blockIdx.x;
    int tid = threadIdx.x;
    int tx = tid & 15, ty = tid >> 4;

    const float* Ab = A + (size_t)(bi * 64) * lda;
    const float* Bb = B + (size_t)(bj * 64) * ldb;

    int arow = tid >> 2, akk = (tid & 3) << 2;

    float acc[4][4];
#pragma unroll
    for (int i = 0; i < 4; i++)
#pragma unroll
        for (int j = 0; j < 4; j++) acc[i][j] = 0.f;

    for (int k0 = 0; k0 < K; k0 += 16) {
        float4 va = *(const float4*)(Ab + (size_t)arow * lda + k0 + akk);
        float4 vb = *(const float4*)(Bb + (size_t)arow * ldb + k0 + akk);
        As[akk + 0][arow] = va.x; As[akk + 1][arow] = va.y;
        As[akk + 2][arow] = va.z; As[akk + 3][arow] = va.w;
        Bs[akk + 0][arow] = vb.x; Bs[akk + 1][arow] = vb.y;
        Bs[akk + 2][arow] = vb.z; Bs[akk + 3][arow] = vb.w;
        __syncthreads();
#pragma unroll
        for (int kk = 0; kk < 16; kk++) {
            float4 a = *(const float4*)&As[kk][ty * 4];
            float4 b = *(const float4*)&Bs[kk][tx * 4];
            float av[4] = {a.x, a.y, a.z, a.w};
            float bv[4] = {b.x, b.y, b.z, b.w};
#pragma unroll
            for (int i = 0; i < 4; i++)
#pragma unroll
                for (int j = 0; j < 4; j++)
                    acc[i][j] += av[i] * bv[j];
        }
        __syncthreads();
    }

#pragma unroll
    for (int i = 0; i < 4; i++) {
        int row = bi * 64 + ty * 4 + i;
#pragma unroll
        for (int j = 0; j < 4; j++) {
            int col = bj * 64 + tx * 4 + j;
            float v = acc[i][j];
            Cs[(size_t)row * ldcs + col] = v;
            __nv_bfloat16 h = __float2bfloat16(v);
            Phi[(size_t)row * NB + col] = h;
            Plo[(size_t)row * NB + col] =
                __float2bfloat16(v - __bfloat162float(h));
        }
    }
}

// ==========================================================================
// batched NN GEMM, 128x128 tiles / 8x8 micro-tiles (for D&C inversion)
// ==========================================================================
__global__ __launch_bounds__(256, 1)
void gemm_nn_b128(const float* __restrict__ A, size_t strA, int lda,
                  const float* __restrict__ B, size_t strB, int ldb,
                  float* __restrict__ C, size_t strC, int ldc,
                  int K, float alpha)
{
    A += (size_t)blockIdx.z * strA;
    B += (size_t)blockIdx.z * strB;
    C += (size_t)blockIdx.z * strC;

    __shared__ float As[8][128];
    __shared__ float Bs[8][128];

    int bi = blockIdx.y, bj = blockIdx.x;
    int tid = threadIdx.x;
    int tx = tid & 15, ty = tid >> 4;

    int lrow = tid >> 1;
    int lkk  = (tid & 1) * 4;
    int brow = tid >> 5;
    int bcol = (tid & 31) * 4;

    const float* Ap = A + (size_t)(bi * 128 + lrow) * lda + lkk;
    const float* Bp = B + bj * 128 + bcol;

    float acc[8][8];
#pragma unroll
    for (int i = 0; i < 8; i++)
#pragma unroll
        for (int j = 0; j < 8; j++) acc[i][j] = 0.f;

    for (int k0 = 0; k0 < K; k0 += 8) {
        float4 va = *(const float4*)(Ap + k0);
        float4 vb = *(const float4*)(Bp + (size_t)(k0 + brow) * ldb);
        if (k0) __syncthreads();
        As[lkk + 0][lrow] = va.x; As[lkk + 1][lrow] = va.y;
        As[lkk + 2][lrow] = va.z; As[lkk + 3][lrow] = va.w;
        *(float4*)&Bs[brow][bcol] = vb;
        __syncthreads();
#pragma unroll
        for (int kk = 0; kk < 8; kk++) {
            float4 a0 = *(const float4*)&As[kk][ty * 4];
            float4 a1 = *(const float4*)&As[kk][64 + ty * 4];
            float4 b0 = *(const float4*)&Bs[kk][tx * 4];
            float4 b1 = *(const float4*)&Bs[kk][64 + tx * 4];
            float a[8] = {a0.x, a0.y, a0.z, a0.w, a1.x, a1.y, a1.z, a1.w};
            float b[8] = {b0.x, b0.y, b0.z, b0.w, b1.x, b1.y, b1.z, b1.w};
#pragma unroll
            for (int i = 0; i < 8; i++)
#pragma unroll
                for (int j = 0; j < 8; j++)
                    acc[i][j] += a[i] * b[j];
        }
    }

#pragma unroll
    for (int i = 0; i < 8; i++) {
        int r = bi * 128 + ((i < 4) ? ty * 4 + i : 64 + ty * 4 + (i - 4));
#pragma unroll
        for (int j = 0; j < 8; j++) {
            int cc = bj * 128 + ((j < 4) ? tx * 4 + j : 64 + tx * 4 + (j - 4));
            C[(size_t)r * ldc + cc] = alpha * acc[i][j];
        }
    }
}

// ==========================================================================
__global__ void zero_kernel(float* p, int n)
{
    for (int i = blockIdx.x * blockDim.x + threadIdx.x; i < n;
         i += gridDim.x * blockDim.x)
        p[i] = 0.f;
}

__global__ void copy_diag_kernel()
{
    int kb = blockIdx.y;
    int idx = blockIdx.x * 256 + threadIdx.x;
    int i = idx >> 7, j = idx & 127;
    g_W[(size_t)(kb * NB + i) * N + kb * NB + j] =
        g_invD[(size_t)kb * NB * NB + idx];
}

__global__ void fnorm_kernel()
{
    __shared__ float red[256];
    float s = 0.f;
    size_t total = (size_t)N * N;
    for (size_t i = blockIdx.x * blockDim.x + threadIdx.x; i < total;
         i += (size_t)gridDim.x * blockDim.x) {
        float v = g_W[i];
        s += v * v;
    }
    red[threadIdx.x] = s; __syncthreads();
    for (int o = 128; o > 0; o >>= 1) {
        if (threadIdx.x < o) red[threadIdx.x] += red[threadIdx.x + o];
        __syncthreads();
    }
    if (threadIdx.x == 0) atomicAdd(&g_scal[0], red[0]);
}

__global__ void proj_kernel(const float* __restrict__ c)
{
    __shared__ float red[256];
    int r = blockIdx.x;
    const float* row = g_W + (size_t)r * N;
    float s = 0.f;
    for (int j = threadIdx.x; j < N; j += 256) s += row[j] * c[j];
    red[threadIdx.x] = s; __syncthreads();
    for (int o = 128; o > 0; o >>= 1) {
        if (threadIdx.x < o) red[threadIdx.x] += red[threadIdx.x + o];
        __syncthreads();
    }
    if (threadIdx.x == 0) {
        float y = red[0];
        atomicAdd(&g_scal[1], y * y);
    }
}

__global__ void final_kernel(float* out)
{
    __shared__ float red[256];
    float s = 0.f;
    for (int i = threadIdx.x; i < N; i += 256)
        s += logf(g_S[(size_t)i * N + i]);
    red[threadIdx.x] = s; __syncthreads();
    for (int o = 128; o > 0; o >>= 1) {
        if (threadIdx.x < o) red[threadIdx.x] += red[threadIdx.x + o];
        __syncthreads();
    }
    if (threadIdx.x == 0) {
        float nrd = expf(red[0] * (2.0f / (float)N));
        out[0] = (float)N / 5.0f +
                 nrd * ((0.5f - 1.0f / PI_F) * g_scal[0] + g_scal[1] / PI_F);
    }
}

// ==========================================================================
// host orchestration
// ==========================================================================
extern "C" void kernel_launch(void* const* d_in, const int* in_sizes, int n_in,
                              void* d_out, int out_size)
{
    (void)in_sizes; (void)n_in; (void)out_size;
    const float* x     = (const float*)d_in[0];
    const float* c     = (const float*)d_in[1];
    const float* alpha = (const float*)d_in[2];
    float* out = (float*)d_out;

    float *Sp, *Wp, *iDp, *T2p, *scalp;
    __nv_bfloat16 *hip, *lop, *Phip, *Plop;
    cudaGetSymbolAddress((void**)&Sp,    g_S);
    cudaGetSymbolAddress((void**)&Wp,    g_W);
    cudaGetSymbolAddress((void**)&iDp,   g_invD);
    cudaGetSymbolAddress((void**)&T2p,   g_T2);
    cudaGetSymbolAddress((void**)&scalp, g_scal);
    cudaGetSymbolAddress((void**)&hip,   g_hi);
    cudaGetSymbolAddress((void**)&lop,   g_lo);
    cudaGetSymbolAddress((void**)&Phip,  g_Phi);
    cudaGetSymbolAddress((void**)&Plop,  g_Plo);

    int potrf_smem = 2 * NB * LDA * (int)sizeof(float);
    cudaFuncSetAttribute(potrf_invert,
                         cudaFuncAttributeMaxDynamicSharedMemorySize,
                         potrf_smem);
    cudaFuncSetAttribute(mma_nt_kernel<2, 0>,
                         cudaFuncAttributeMaxDynamicSharedMemorySize,
                         GRAM_SMEM);
    cudaFuncSetAttribute(mma_nt_kernel<3, 1>,
                         cudaFuncAttributeMaxDynamicSharedMemorySize,
                         GRAM_SMEM);

    // 1. gram via bf16 split mma (2 products, compile-time specialized)
    split_kernel<<<4096, 256>>>(x);
    mma_nt_kernel<2, 0><<<NBLK * (NBLK + 1) / 2, 256, GRAM_SMEM>>>(
        hip, lop, hip, lop, D, Sp, N, D, 1.0f / (float)D);

    // 2. arc-cosine kernel step
    diag_kernel<<<N / 256, 256>>>();
    step_kernel<<<dim3(N / 32, N / 8), dim3(32, 8)>>>(alpha);

    // 3. blocked Cholesky (in place, lower)
    for (int k = 0; k < NBLK; k++) {
        potrf_invert<<<1, PT, potrf_smem>>>(k);
        if (k < NBLK - 1) {
            int rows = (NBLK - 1 - k) * NB;
            gemm_nt_split<<<dim3(2, rows / 64), 256>>>(
                Sp + (size_t)(k + 1) * NB * N + (size_t)k * NB, N,
                iDp + (size_t)k * NB * NB, NB,
                Sp + (size_t)(k + 1) * NB * N + (size_t)k * NB, N,
                Phip, Plop, NB);
            int T2 = NBLK - 1 - k;
            mma_nt_kernel<3, 1><<<T2 * (T2 + 1) / 2, 256, GRAM_SMEM>>>(
                Phip, Plop, Phip, Plop, NB,
                Sp + (size_t)(k + 1) * NB * N + (size_t)(k + 1) * NB, N,
                NB, 1.0f);
        }
    }

    // 4. divide & conquer triangular inversion: W = L^{-1}
    zero_kernel<<<4096, 256>>>(Wp, N * N);
    copy_diag_kernel<<<dim3(64, NBLK), 256>>>();
    for (int lev = 0; lev < 4; lev++) {
        int s = 128 << lev;
        int pairs = N / (2 * s);
        size_t strW = (size_t)2 * s * (N + 1);
        gemm_nn_b128<<<dim3(s / 128, s / 128, pairs), 256>>>(
            Wp + (size_t)s * N + s, strW, N,
            Sp + (size_t)s * N,     strW, N,
            T2p, (size_t)s * s, s,
            s, 1.0f);
        gemm_nn_b128<<<dim3(s / 128, s / 128, pairs), 256>>>(
            T2p, (size_t)s * s, s,
            Wp, strW, N,
            Wp + (size_t)s * N, strW, N,
            s, -1.0f);
    }

    // 5. reductions + final scalar
    zero_kernel<<<1, 32>>>(scalp, 4);
    fnorm_kernel<<<1024, 256>>>();
    proj_kernel<<<N, 256>>>(c);
    final_kernel<<<1, 256>>>(out);
}

// round 13
// speedup vs baseline: 1.6878x; 1.0878x over previous
#include <cuda_runtime.h>
#include <cuda_bf16.h>
#include <math.h>
#include <stdint.h>

#define N 2048
#define D 16384
#define NB 128
#define LDA 129            // padded smem stride (bank-conflict-free columns)
#define NBLK 16            // N / NB
#define PI_F 3.14159265358979323846f

// ---------------- device scratch (no allocations allowed) ----------------
__device__ float g_S[(size_t)N * N];        // gram / sigma / L (lower, in place)
__device__ float g_W[(size_t)N * N];        // L^{-1} (lower)
__device__ float g_invD[NBLK * NB * NB];    // per-panel inv(L11)
__device__ float g_T2[(size_t)1024 * 1024]; // D&C inversion scratch
__device__ float g_diag[N];                 // diag snapshot
__device__ float g_scal[4];                 // [0]=trace acc, [1]=proj acc
__device__ __nv_bfloat16 g_hi[(size_t)N * D];
__device__ __nv_bfloat16 g_lo[(size_t)N * D];
__device__ __nv_bfloat16 g_Phi[(size_t)N * NB];  // TRSM panel, bf16 hi
__device__ __nv_bfloat16 g_Plo[(size_t)N * NB];  // TRSM panel, bf16 lo

// ==========================================================================
__device__ __forceinline__ uint32_t smem_u32(const void* p) {
    uint32_t a;
    asm("{ .reg .u64 t; cvta.to.shared.u64 t, %1; cvt.u32.u64 %0, t; }"
        : "=r"(a) : "l"(p));
    return a;
}

// ==========================================================================
// split conversion: x -> hi (bf16) only (gram uses pure hi*hi; lo unused
// there). g_lo retained for the Cholesky panel path only.
// ==========================================================================
__global__ void split_kernel(const float* __restrict__ x)
{
    size_t total = (size_t)N * D / 4;
    const float4* x4 = (const float4*)x;
    for (size_t i = blockIdx.x * (size_t)blockDim.x + threadIdx.x; i < total;
         i += (size_t)gridDim.x * blockDim.x) {
        float4 v = x4[i];
        __nv_bfloat162* hp = (__nv_bfloat162*)(g_hi + i * 4);
        hp[0] = __nv_bfloat162(__float2bfloat16(v.x), __float2bfloat16(v.y));
        hp[1] = __nv_bfloat162(__float2bfloat16(v.z), __float2bfloat16(v.w));
    }
}

// ==========================================================================
// templated bf16-split NT mma kernel over lower tile pairs:
// NPROD=1: acc = Ahi*Bhi^T                    (gram; only hi tiles loaded)
// NPROD=2: acc += Ahi*Blo^T
// NPROD=3: acc += Alo*Bhi^T as well           (SYRK)
// MODE=0:  C = clip(acc*scale, -1, 1)
// MODE=1:  C -= acc
// ==========================================================================
#define BKG 32
#define GTILE_B (128 * 40 * 2)
#define GRAM_SMEM (2 * 4 * GTILE_B)

__device__ __forceinline__ void ldsm_x4(uint32_t* r, uint32_t addr) {
    asm volatile("ldmatrix.sync.aligned.m8n8.x4.shared.b16 {%0,%1,%2,%3}, [%4];"
                 : "=r"(r[0]), "=r"(r[1]), "=r"(r[2]), "=r"(r[3]) : "r"(addr));
}
__device__ __forceinline__ void ldsm_x2(uint32_t* r, uint32_t addr) {
    asm volatile("ldmatrix.sync.aligned.m8n8.x2.shared.b16 {%0,%1}, [%2];"
                 : "=r"(r[0]), "=r"(r[1]) : "r"(addr));
}
__device__ __forceinline__ void mma_bf16(float* d, const uint32_t* a,
                                         const uint32_t* b) {
    asm volatile(
        "mma.sync.aligned.m16n8k16.row.col.f32.bf16.bf16.f32 "
        "{%0,%1,%2,%3}, {%4,%5,%6,%7}, {%8,%9}, {%0,%1,%2,%3};"
        : "+f"(d[0]), "+f"(d[1]), "+f"(d[2]), "+f"(d[3])
        : "r"(a[0]), "r"(a[1]), "r"(a[2]), "r"(a[3]), "r"(b[0]), "r"(b[1]));
}
#define CP_ASYNC(dst, src) \
    asm volatile("cp.async.cg.shared.global [%0], [%1], 16;" \
                 :: "r"(dst), "l"(src))
#define CP_COMMIT() asm volatile("cp.async.commit_group;" ::: "memory")

template <int NPROD, int MODE>
__global__ __launch_bounds__(256, 1)
void mma_nt_kernel(const __nv_bfloat16* __restrict__ Ahi,
                   const __nv_bfloat16* __restrict__ Alo,
                   const __nv_bfloat16* __restrict__ Bhi,
                   const __nv_bfloat16* __restrict__ Blo,
                   size_t lda, float* __restrict__ Cbase, int ldc,
                   int K, float scale)
{
    extern __shared__ char dsm[];
    uint32_t sbase = smem_u32(dsm);

    int tid  = threadIdx.x;
    int wid  = tid >> 5;
    int lane = tid & 31;

    int t = blockIdx.x;
    int bi = (int)((sqrtf(8.f * (float)t + 1.f) - 1.f) * 0.5f);
    while ((bi + 1) * (bi + 2) / 2 <= t) bi++;
    while (bi * (bi + 1) / 2 > t) bi--;
    int bj = t - bi * (bi + 1) / 2;

    const __nv_bfloat16* srcs[4] = {
        Ahi + (size_t)bi * 128 * lda,
        Alo + (size_t)bi * 128 * lda,
        Bhi + (size_t)bj * 128 * lda,
        Blo + (size_t)bj * 128 * lda
    };

    int m0w = (wid & 1) * 64;
    int n0w = (wid >> 1) * 32;

    float acc[4][4][4];
#pragma unroll
    for (int im = 0; im < 4; im++)
#pragma unroll
        for (int jn = 0; jn < 4; jn++)
#pragma unroll
            for (int e = 0; e < 4; e++) acc[im][jn][e] = 0.f;

    const int S = K / BKG;

    {
#pragma unroll
        for (int it = 0; it < 8; it++) {
            int idx = tid + it * 256;
            int tile = idx >> 9;
            int rem = idx & 511;
            int r = rem >> 2, ch = rem & 3;
            if (NPROD == 1 && (tile & 1)) continue;  // no lo tiles at all
            if (NPROD == 2 && tile == 1) continue;   // Alo unused
            uint32_t dst = sbase + (uint32_t)tile * GTILE_B + r * 80 + ch * 16;
            CP_ASYNC(dst, srcs[tile] + (size_t)r * lda + ch * 8);
        }
        CP_COMMIT();
    }

#pragma unroll 1
    for (int s = 0; s < S; s++) {
        if (s + 1 < S) {
            int k0 = (s + 1) * BKG;
            uint32_t boff = (uint32_t)((s + 1) & 1) * (4 * GTILE_B);
#pragma unroll
            for (int it = 0; it < 8; it++) {
                int idx = tid + it * 256;
                int tile = idx >> 9;
                int rem = idx & 511;
                int r = rem >> 2, ch = rem & 3;
                if (NPROD == 1 && (tile & 1)) continue;
                if (NPROD == 2 && tile == 1) continue;
                uint32_t dst = sbase + boff + (uint32_t)tile * GTILE_B +
                               r * 80 + ch * 16;
                CP_ASYNC(dst, srcs[tile] + (size_t)r * lda + k0 + ch * 8);
            }
            CP_COMMIT();
            asm volatile("cp.async.wait_group 1;" ::: "memory");
        } else {
            asm volatile("cp.async.wait_group 0;" ::: "memory");
        }
        __syncthreads();

        uint32_t buf = sbase + (uint32_t)(s & 1) * (4 * GTILE_B);
        uint32_t Ahi_b = buf;
        uint32_t Alo_b = buf + GTILE_B;
        uint32_t Bhi_b = buf + 2 * GTILE_B;
        uint32_t Blo_b = buf + 3 * GTILE_B;

#pragma unroll
        for (int ks = 0; ks < 2; ks++) {
            int kof = ks * 16;
            int arow = lane & 15;
            int acol = kof + 8 * (lane >> 4);
            uint32_t ah[4][4], al[4][4];
#pragma unroll
            for (int im = 0; im < 4; im++) {
                uint32_t ro = (uint32_t)(m0w + im * 16 + arow) * 80 + acol * 2;
                ldsm_x4(ah[im], Ahi_b + ro);
                if (NPROD == 3) ldsm_x4(al[im], Alo_b + ro);
            }
            int brow = lane & 7;
            int bcol = kof + 8 * ((lane >> 3) & 1);
            uint32_t bh[4][2], bl[4][2];
#pragma unroll
            for (int jn = 0; jn < 4; jn++) {
                uint32_t ro = (uint32_t)(n0w + jn * 8 + brow) * 80 + bcol * 2;
                ldsm_x2(bh[jn], Bhi_b + ro);
                if (NPROD >= 2) ldsm_x2(bl[jn], Blo_b + ro);
            }
#pragma unroll
            for (int im = 0; im < 4; im++)
#pragma unroll
                for (int jn = 0; jn < 4; jn++) {
                    mma_bf16(acc[im][jn], ah[im], bh[jn]);
                    if (NPROD >= 2) mma_bf16(acc[im][jn], ah[im], bl[jn]);
                    if (NPROD == 3) mma_bf16(acc[im][jn], al[im], bh[jn]);
                }
        }
        __syncthreads();
    }

#pragma unroll
    for (int im = 0; im < 4; im++) {
        int row = bi * 128 + m0w + im * 16 + (lane >> 2);
#pragma unroll
        for (int jn = 0; jn < 4; jn++) {
            int col = bj * 128 + n0w + jn * 8 + (lane & 3) * 2;
            float* p0 = Cbase + (size_t)row * ldc + col;
            float* p1 = Cbase + (size_t)(row + 8) * ldc + col;
            if (MODE == 0) {
                p0[0] = fminf(fmaxf(acc[im][jn][0] * scale, -1.f), 1.f);
                p0[1] = fminf(fmaxf(acc[im][jn][1] * scale, -1.f), 1.f);
                p1[0] = fminf(fmaxf(acc[im][jn][2] * scale, -1.f), 1.f);
                p1[1] = fminf(fmaxf(acc[im][jn][3] * scale, -1.f), 1.f);
            } else {
                p0[0] -= acc[im][jn][0];
                p0[1] -= acc[im][jn][1];
                p1[0] -= acc[im][jn][2];
                p1[1] -= acc[im][jn][3];
            }
        }
    }
}

// ==========================================================================
__global__ void diag_kernel()
{
    int i = blockIdx.x * blockDim.x + threadIdx.x;
    if (i < N) g_diag[i] = g_S[(size_t)i * N + i];
}

__global__ void step_kernel(const float* __restrict__ alpha_p)
{
    int j = blockIdx.x * 32 + threadIdx.x;
    int i = blockIdx.y * 8 + threadIdx.y;
    if (i >= N || j > i) return;
    float a  = *alpha_p;
    float a2 = a * a;
    float cross = sqrtf(g_diag[i] * g_diag[j]);
    float s = g_S[(size_t)i * N + j];
    float m = fminf(fmaxf(s / cross, -1.f), 1.f);
    float q = 1.f - m * m;
    float sq, ac;
    if (q > 0.f) { sq = sqrtf(q); ac = acosf(m); }
    else         { sq = 0.f;      ac = (m > 0.f) ? 0.f : PI_F; }
    float f  = (sq + m * (PI_F - ac)) / PI_F;
    float ts = cross * f;
    float ov = (s + a2 * ts) / (1.f + a2);
    g_S[(size_t)i * N + j] = fminf(fmaxf(ov, -1.f), 1.f);
}

// ==========================================================================
// panel factorization + inversion of 128x128 diag block (512 threads).
// ==========================================================================
#define PT 512
__global__ __launch_bounds__(PT, 1)
void potrf_invert(int kb)
{
    extern __shared__ float sh[];
    float* A = sh;                 // NB x NB stride LDA (L, lower)
    float* W = sh + NB * LDA;      // NB x NB stride LDA (inv(L), lower)
    __shared__ float Ts[3 * 1056];
    int tid = threadIdx.x;
    int base = kb * NB;

    for (int idx = tid; idx < NB * 32; idx += PT) {
        int i = idx >> 5, j4 = (idx & 31) << 2;
        float4 v = *(const float4*)&g_S[(size_t)(base + i) * N + base + j4];
        A[i * LDA + j4 + 0] = v.x;
        A[i * LDA + j4 + 1] = v.y;
        A[i * LDA + j4 + 2] = v.z;
        A[i * LDA + j4 + 3] = v.w;
    }
    __syncthreads();

    for (int p = 0; p < 4; p++) {
        int off = p * 32;

        if (tid < 32) {
            const unsigned FULL = 0xffffffffu;
            int r = tid;
            float ar[32];
#pragma unroll
            for (int t = 0; t < 32; t++)
                ar[t] = (t <= r) ? A[(off + r) * LDA + off + t] : 0.f;
            float rs_reg = 0.f;
#pragma unroll
            for (int j = 0; j < 32; j++) {
                float d   = __shfl_sync(FULL, ar[j], j);
                float rsj = rsqrtf(d);
                float lj  = ar[j] * rsj;
                ar[j] = lj;
                if (r == j) rs_reg = rsj;
#pragma unroll
                for (int t = j + 1; t < 32; t++) {
                    float ltj = __shfl_sync(FULL, lj, t);
                    ar[t] -= lj * ltj;
                }
            }
            int c = r;
            float w[32];
#pragma unroll
            for (int t = 0; t < 32; t++) w[t] = 0.f;
#pragma unroll
            for (int i = 0; i < 32; i++) {
                float s = (i == c) ? 1.f : 0.f;
#pragma unroll
                for (int t = 0; t < i; t++) {
                    float lit = __shfl_sync(FULL, ar[t], i);
                    s -= lit * w[t];
                }
                float rsi = __shfl_sync(FULL, rs_reg, i);
                w[i] = (i >= c) ? s * rsi : 0.f;
            }
#pragma unroll
            for (int t = 0; t < 32; t++)
                if (t <= r) A[(off + r) * LDA + off + t] = ar[t];
#pragma unroll
            for (int i = 0; i < 32; i++)
                W[(off + i) * LDA + off + c] = w[i];
        }
        __syncthreads();

        int nr = NB - off - 32;
        if (nr > 0) {
            int ntr = (nr >> 2) * 8;
            float acc[4][4];
            int tr = 0, tc = 0;
            if (tid < ntr) {
                tr = (tid >> 3) * 4;
                tc = (tid & 7) * 4;
#pragma unroll
                for (int r = 0; r < 4; r++)
#pragma unroll
                    for (int cidx = 0; cidx < 4; cidx++) acc[r][cidx] = 0.f;
#pragma unroll 8
                for (int k = 0; k < 32; k++) {
                    float av[4], wv[4];
#pragma unroll
                    for (int r = 0; r < 4; r++)
                        av[r] = A[(off + 32 + tr + r) * LDA + off + k];
#pragma unroll
                    for (int cidx = 0; cidx < 4; cidx++)
                        wv[cidx] = W[(off + tc + cidx) * LDA + off + k];
#pragma unroll
                    for (int r = 0; r < 4; r++)
#pragma unroll
                        for (int cidx = 0; cidx < 4; cidx++)
                            acc[r][cidx] += av[r] * wv[cidx];
                }
            }
            __syncthreads();
            if (tid < ntr) {
#pragma unroll
                for (int r = 0; r < 4; r++)
#pragma unroll
                    for (int cidx = 0; cidx < 4; cidx++)
                        A[(off + 32 + tr + r) * LDA + off + tc + cidx] =
                            acc[r][cidx];
            }
            __syncthreads();

            int nt = nr >> 2;
            int ntot = nt * (nt + 1) / 2;
            for (int tId = tid; tId < ntot; tId += PT) {
                int ti = (int)((sqrtf(8.f * (float)tId + 1.f) - 1.f) * 0.5f);
                while ((ti + 1) * (ti + 2) / 2 <= tId) ti++;
                while (ti * (ti + 1) / 2 > tId) ti--;
                int tj = tId - ti * (ti + 1) / 2;
                int i0 = off + 32 + ti * 4;
                int t0 = off + 32 + tj * 4;
                float a2[4][4];
#pragma unroll
                for (int r = 0; r < 4; r++)
#pragma unroll
                    for (int cidx = 0; cidx < 4; cidx++) a2[r][cidx] = 0.f;
#pragma unroll 8
                for (int k = 0; k < 32; k++) {
                    float av[4], bv[4];
#pragma unroll
                    for (int r = 0; r < 4; r++)
                        av[r] = A[(i0 + r) * LDA + off + k];
#pragma unroll
                    for (int cidx = 0; cidx < 4; cidx++)
                        bv[cidx] = A[(t0 + cidx) * LDA + off + k];
#pragma unroll
                    for (int r = 0; r < 4; r++)
#pragma unroll
                        for (int cidx = 0; cidx < 4; cidx++)
                            a2[r][cidx] += av[r] * bv[cidx];
                }
#pragma unroll
                for (int r = 0; r < 4; r++)
#pragma unroll
                    for (int cidx = 0; cidx < 4; cidx++) {
                        int ii = i0 + r, tt = t0 + cidx;
                        if (tt <= ii) A[ii * LDA + tt] -= a2[r][cidx];
                    }
            }
            __syncthreads();
        }
    }

    for (int ib = 1; ib < 4; ib++) {
        for (int tId = tid; tId < ib * 64; tId += PT) {
            int j = tId >> 6;
            int e = tId & 63;
            int r0 = (e >> 3) * 4, c0 = (e & 7) * 4;
            float acc[4][4];
#pragma unroll
            for (int r = 0; r < 4; r++)
#pragma unroll
                for (int cidx = 0; cidx < 4; cidx++) acc[r][cidx] = 0.f;
            for (int tb = j; tb < ib; tb++) {
#pragma unroll 8
                for (int k = 0; k < 32; k++) {
                    float lv[4], wv[4];
#pragma unroll
                    for (int r = 0; r < 4; r++)
                        lv[r] = A[(32 * ib + r0 + r) * LDA + 32 * tb + k];
#pragma unroll
                    for (int cidx = 0; cidx < 4; cidx++)
                        wv[cidx] = W[(32 * tb + k) * LDA + 32 * j + c0 + cidx];
#pragma unroll
                    for (int r = 0; r < 4; r++)
#pragma unroll
                        for (int cidx = 0; cidx < 4; cidx++)
                            acc[r][cidx] += lv[r] * wv[cidx];
                }
            }
#pragma unroll
            for (int r = 0; r < 4; r++)
#pragma unroll
                for (int cidx = 0; cidx < 4; cidx++)
                    Ts[j * 1056 + (r0 + r) * 33 + c0 + cidx] = acc[r][cidx];
        }
        __syncthreads();
        for (int tId = tid; tId < ib * 64; tId += PT) {
            int j = tId >> 6;
            int e = tId & 63;
            int r0 = (e >> 3) * 4, c0 = (e & 7) * 4;
            float acc[4][4];
#pragma unroll
            for (int r = 0; r < 4; r++)
#pragma unroll
                for (int cidx = 0; cidx < 4; cidx++) acc[r][cidx] = 0.f;
#pragma unroll 8
            for (int k = 0; k < 32; k++) {
                float wv[4], tv[4];
#pragma unroll
                for (int r = 0; r < 4; r++)
                    wv[r] = W[(32 * ib + r0 + r) * LDA + 32 * ib + k];
#pragma unroll
                for (int cidx = 0; cidx < 4; cidx++)
                    tv[cidx] = Ts[j * 1056 + k * 33 + c0 + cidx];
#pragma unroll
                for (int r = 0; r < 4; r++)
#pragma unroll
                    for (int cidx = 0; cidx < 4; cidx++)
                        acc[r][cidx] += wv[r] * tv[cidx];
            }
#pragma unroll
            for (int r = 0; r < 4; r++)
#pragma unroll
                for (int cidx = 0; cidx < 4; cidx++)
                    W[(32 * ib + r0 + r) * LDA + 32 * j + c0 + cidx] =
                        -acc[r][cidx];
        }
        __syncthreads();
    }

    for (int idx = tid; idx < NB * NB; idx += PT) {
        int i = idx >> 7, j = idx & 127;
        if (j <= i) g_S[(size_t)(base + i) * N + base + j] = A[i * LDA + j];
        g_invD[(size_t)kb * NB * NB + idx] =
            ((j >> 5) <= (i >> 5)) ? W[i * LDA + j] : 0.f;
    }
}

// ==========================================================================
// TRSM panel GEMM: C = A * B^T (64x64 tiles); writes fp32 L into S and
// bf16 hi/lo split panels for the mma SYRK.
// ==========================================================================
__global__ __launch_bounds__(256, 2)
void gemm_nt_split(const float* __restrict__ A, int lda,
                   const float* __restrict__ B, int ldb,
                   float* __restrict__ Cs, int ldcs,
                   __nv_bfloat16* __restrict__ Phi,
                   __nv_bfloat16* __restrict__ Plo, int K)
{
    __shared__ float As[16][64];
    __shared__ float Bs[16][64];
    int bi = blockIdx.y, bj = blockIdx.x;
    int tid = threadIdx.x;
    int tx = tid & 15, ty = tid >> 4;

    const float* Ab = A + (size_t)(bi * 64) * lda;
    const float* Bb = B + (size_t)(bj * 64) * ldb;

    int arow = tid >> 2, akk = (tid & 3) << 2;

    float acc[4][4];
#pragma unroll
    for (int i = 0; i < 4; i++)
#pragma unroll
        for (int j = 0; j < 4; j++) acc[i][j] = 0.f;

    for (int k0 = 0; k0 < K; k0 += 16) {
        float4 va = *(const float4*)(Ab + (size_t)arow * lda + k0 + akk);
        float4 vb = *(const float4*)(Bb + (size_t)arow * ldb + k0 + akk);
        As[akk + 0][arow] = va.x; As[akk + 1][arow] = va.y;
        As[akk + 2][arow] = va.z; As[akk + 3][arow] = va.w;
        Bs[akk + 0][arow] = vb.x; Bs[akk + 1][arow] = vb.y;
        Bs[akk + 2][arow] = vb.z; Bs[akk + 3][arow] = vb.w;
        __syncthreads();
#pragma unroll
        for (int kk = 0; kk < 16; kk++) {
            float4 a = *(const float4*)&As[kk][ty * 4];
            float4 b = *(const float4*)&Bs[kk][tx * 4];
            float av[4] = {a.x, a.y, a.z, a.w};
            float bv[4] = {b.x, b.y, b.z, b.w};
#pragma unroll
            for (int i = 0; i < 4; i++)
#pragma unroll
                for (int j = 0; j < 4; j++)
                    acc[i][j] += av[i] * bv[j];
        }
        __syncthreads();
    }

#pragma unroll
    for (int i = 0; i < 4; i++) {
        int row = bi * 64 + ty * 4 + i;
#pragma unroll
        for (int j = 0; j < 4; j++) {
            int col = bj * 64 + tx * 4 + j;
            float v = acc[i][j];
            Cs[(size_t)row * ldcs + col] = v;
            __nv_bfloat16 h = __float2bfloat16(v);
            Phi[(size_t)row * NB + col] = h;
            Plo[(size_t)row * NB + col] =
                __float2bfloat16(v - __bfloat162float(h));
        }
    }
}

// ==========================================================================
// batched NN GEMM, 128x128 tiles / 8x8 micro-tiles (for D&C inversion)
// ==========================================================================
__global__ __launch_bounds__(256, 1)
void gemm_nn_b128(const float* __restrict__ A, size_t strA, int lda,
                  const float* __restrict__ B, size_t strB, int ldb,
                  float* __restrict__ C, size_t strC, int ldc,
                  int K, float alpha)
{
    A += (size_t)blockIdx.z * strA;
    B += (size_t)blockIdx.z * strB;
    C += (size_t)blockIdx.z * strC;

    __shared__ float As[8][128];
    __shared__ float Bs[8][128];

    int bi = blockIdx.y, bj = blockIdx.x;
    int tid = threadIdx.x;
    int tx = tid & 15, ty = tid >> 4;

    int lrow = tid >> 1;
    int lkk  = (tid & 1) * 4;
    int brow = tid >> 5;
    int bcol = (tid & 31) * 4;

    const float* Ap = A + (size_t)(bi * 128 + lrow) * lda + lkk;
    const float* Bp = B + bj * 128 + bcol;

    float acc[8][8];
#pragma unroll
    for (int i = 0; i < 8; i++)
#pragma unroll
        for (int j = 0; j < 8; j++) acc[i][j] = 0.f;

    for (int k0 = 0; k0 < K; k0 += 8) {
        float4 va = *(const float4*)(Ap + k0);
        float4 vb = *(const float4*)(Bp + (size_t)(k0 + brow) * ldb);
        if (k0) __syncthreads();
        As[lkk + 0][lrow] = va.x; As[lkk + 1][lrow] = va.y;
        As[lkk + 2][lrow] = va.z; As[lkk + 3][lrow] = va.w;
        *(float4*)&Bs[brow][bcol] = vb;
        __syncthreads();
#pragma unroll
        for (int kk = 0; kk < 8; kk++) {
            float4 a0 = *(const float4*)&As[kk][ty * 4];
            float4 a1 = *(const float4*)&As[kk][64 + ty * 4];
            float4 b0 = *(const float4*)&Bs[kk][tx * 4];
            float4 b1 = *(const float4*)&Bs[kk][64 + tx * 4];
            float a[8] = {a0.x, a0.y, a0.z, a0.w, a1.x, a1.y, a1.z, a1.w};
            float b[8] = {b0.x, b0.y, b0.z, b0.w, b1.x, b1.y, b1.z, b1.w};
#pragma unroll
            for (int i = 0; i < 8; i++)
#pragma unroll
                for (int j = 0; j < 8; j++)
                    acc[i][j] += a[i] * b[j];
        }
    }

#pragma unroll
    for (int i = 0; i < 8; i++) {
        int r = bi * 128 + ((i < 4) ? ty * 4 + i : 64 + ty * 4 + (i - 4));
#pragma unroll
        for (int j = 0; j < 8; j++) {
            int cc = bj * 128 + ((j < 4) ? tx * 4 + j : 64 + tx * 4 + (j - 4));
            C[(size_t)r * ldc + cc] = alpha * acc[i][j];
        }
    }
}

// ==========================================================================
__global__ void zero_kernel(float* p, int n)
{
    for (int i = blockIdx.x * blockDim.x + threadIdx.x; i < n;
         i += gridDim.x * blockDim.x)
        p[i] = 0.f;
}

__global__ void copy_diag_kernel()
{
    int kb = blockIdx.y;
    int idx = blockIdx.x * 256 + threadIdx.x;
    int i = idx >> 7, j = idx & 127;
    g_W[(size_t)(kb * NB + i) * N + kb * NB + j] =
        g_invD[(size_t)kb * NB * NB + idx];
}

// ==========================================================================
// fused reduction over lower-triangular W:
//   trace(inv) = ||W||_F^2,  proj = sum_r (W_row_r . c)^2
// one block per row; reads only j <= r.
// ==========================================================================
__global__ void reduce_kernel(const float* __restrict__ c)
{
    __shared__ float r2[256], ry[256];
    int r = blockIdx.x;
    const float* row = g_W + (size_t)r * N;
    float s2 = 0.f, sy = 0.f;
    for (int j = threadIdx.x; j <= r; j += 256) {
        float v = row[j];
        s2 += v * v;
        sy += v * c[j];
    }
    r2[threadIdx.x] = s2; ry[threadIdx.x] = sy;
    __syncthreads();
    for (int o = 128; o > 0; o >>= 1) {
        if (threadIdx.x < o) {
            r2[threadIdx.x] += r2[threadIdx.x + o];
            ry[threadIdx.x] += ry[threadIdx.x + o];
        }
        __syncthreads();
    }
    if (threadIdx.x == 0) {
        atomicAdd(&g_scal[0], r2[0]);
        float y = ry[0];
        atomicAdd(&g_scal[1], y * y);
    }
}

__global__ void final_kernel(float* out)
{
    __shared__ float red[256];
    float s = 0.f;
    for (int i = threadIdx.x; i < N; i += 256)
        s += logf(g_S[(size_t)i * N + i]);
    red[threadIdx.x] = s; __syncthreads();
    for (int o = 128; o > 0; o >>= 1) {
        if (threadIdx.x < o) red[threadIdx.x] += red[threadIdx.x + o];
        __syncthreads();
    }
    if (threadIdx.x == 0) {
        float nrd = expf(red[0] * (2.0f / (float)N));
        out[0] = (float)N / 5.0f +
                 nrd * ((0.5f - 1.0f / PI_F) * g_scal[0] + g_scal[1] / PI_F);
    }
}

// ==========================================================================
// host orchestration
// ==========================================================================
extern "C" void kernel_launch(void* const* d_in, const int* in_sizes, int n_in,
                              void* d_out, int out_size)
{
    (void)in_sizes; (void)n_in; (void)out_size;
    const float* x     = (const float*)d_in[0];
    const float* c     = (const float*)d_in[1];
    const float* alpha = (const float*)d_in[2];
    float* out = (float*)d_out;

    float *Sp, *Wp, *iDp, *T2p, *scalp;
    __nv_bfloat16 *hip, *lop, *Phip, *Plop;
    cudaGetSymbolAddress((void**)&Sp,    g_S);
    cudaGetSymbolAddress((void**)&Wp,    g_W);
    cudaGetSymbolAddress((void**)&iDp,   g_invD);
    cudaGetSymbolAddress((void**)&T2p,   g_T2);
    cudaGetSymbolAddress((void**)&scalp, g_scal);
    cudaGetSymbolAddress((void**)&hip,   g_hi);
    cudaGetSymbolAddress((void**)&lop,   g_lo);
    cudaGetSymbolAddress((void**)&Phip,  g_Phi);
    cudaGetSymbolAddress((void**)&Plop,  g_Plo);

    int potrf_smem = 2 * NB * LDA * (int)sizeof(float);
    cudaFuncSetAttribute(potrf_invert,
                         cudaFuncAttributeMaxDynamicSharedMemorySize,
                         potrf_smem);
    cudaFuncSetAttribute(mma_nt_kernel<1, 0>,
                         cudaFuncAttributeMaxDynamicSharedMemorySize,
                         GRAM_SMEM);
    cudaFuncSetAttribute(mma_nt_kernel<3, 1>,
                         cudaFuncAttributeMaxDynamicSharedMemorySize,
                         GRAM_SMEM);

    // 1. gram via pure-hi bf16 mma (1 product)
    split_kernel<<<4096, 256>>>(x);
    mma_nt_kernel<1, 0><<<NBLK * (NBLK + 1) / 2, 256, GRAM_SMEM>>>(
        hip, lop, hip, lop, D, Sp, N, D, 1.0f / (float)D);

    // 2. arc-cosine kernel step
    diag_kernel<<<N / 256, 256>>>();
    step_kernel<<<dim3(N / 32, N / 8), dim3(32, 8)>>>(alpha);

    // 3. blocked Cholesky (in place, lower)
    for (int k = 0; k < NBLK; k++) {
        potrf_invert<<<1, PT, potrf_smem>>>(k);
        if (k < NBLK - 1) {
            int rows = (NBLK - 1 - k) * NB;
            gemm_nt_split<<<dim3(2, rows / 64), 256>>>(
                Sp + (size_t)(k + 1) * NB * N + (size_t)k * NB, N,
                iDp + (size_t)k * NB * NB, NB,
                Sp + (size_t)(k + 1) * NB * N + (size_t)k * NB, N,
                Phip, Plop, NB);
            int T2 = NBLK - 1 - k;
            mma_nt_kernel<3, 1><<<T2 * (T2 + 1) / 2, 256, GRAM_SMEM>>>(
                Phip, Plop, Phip, Plop, NB,
                Sp + (size_t)(k + 1) * NB * N + (size_t)(k + 1) * NB, N,
                NB, 1.0f);
        }
    }

    // 4. divide & conquer triangular inversion: W = L^{-1}
    zero_kernel<<<4096, 256>>>(Wp, N * N);
    copy_diag_kernel<<<dim3(64, NBLK), 256>>>();
    for (int lev = 0; lev < 4; lev++) {
        int s = 128 << lev;
        int pairs = N / (2 * s);
        size_t strW = (size_t)2 * s * (N + 1);
        gemm_nn_b128<<<dim3(s / 128, s / 128, pairs), 256>>>(
            Wp + (size_t)s * N + s, strW, N,
            Sp + (size_t)s * N,     strW, N,
            T2p, (size_t)s * s, s,
            s, 1.0f);
        gemm_nn_b128<<<dim3(s / 128, s / 128, pairs), 256>>>(
            T2p, (size_t)s * s, s,
            Wp, strW, N,
            Wp + (size_t)s * N, strW, N,
            s, -1.0f);
    }

    // 5. fused reductions + final scalar
    zero_kernel<<<1, 32>>>(scalp, 4);
    reduce_kernel<<<N, 256>>>(c);
    final_kernel<<<1, 256>>>(out);
}

// round 14
// speedup vs baseline: 2.0425x; 1.2102x over previous
#include <cuda_runtime.h>
#include <cuda_bf16.h>
#include <math.h>
#include <stdint.h>

#define N 2048
#define D 16384
#define NB 128
#define LDA 129            // padded smem stride (bank-conflict-free columns)
#define NBLK 16            // N / NB
#define PI_F 3.14159265358979323846f

// ---------------- device scratch (no allocations allowed) ----------------
__device__ float g_S[(size_t)N * N];        // gram / sigma / L (lower, in place)
__device__ float g_W[(size_t)N * N];        // L^{-1} (lower)
__device__ float g_invD[NBLK * NB * NB];    // per-panel inv(L11)
__device__ float g_T2[(size_t)1024 * 1024]; // D&C inversion scratch
__device__ float g_diag[N];                 // diag snapshot
__device__ float g_scal[4];                 // [0]=trace acc, [1]=proj acc
__device__ __nv_bfloat16 g_hi[(size_t)N * D];
__device__ __nv_bfloat16 g_lo[(size_t)N * D];
__device__ __nv_bfloat16 g_Phi[(size_t)N * NB];  // TRSM panel, bf16 hi
__device__ __nv_bfloat16 g_Plo[(size_t)N * NB];  // TRSM panel, bf16 lo

// ==========================================================================
__device__ __forceinline__ uint32_t smem_u32(const void* p) {
    uint32_t a;
    asm("{ .reg .u64 t; cvta.to.shared.u64 t, %1; cvt.u32.u64 %0, t; }"
        : "=r"(a) : "l"(p));
    return a;
}
__device__ __forceinline__ uint32_t bf2pack(float a, float b) {
    __nv_bfloat162 h(__float2bfloat16(a), __float2bfloat16(b));
    return *(uint32_t*)&h;
}

// ==========================================================================
// split conversion: x -> hi (bf16) only (gram is pure hi*hi)
// ==========================================================================
__global__ void split_kernel(const float* __restrict__ x)
{
    size_t total = (size_t)N * D / 4;
    const float4* x4 = (const float4*)x;
    for (size_t i = blockIdx.x * (size_t)blockDim.x + threadIdx.x; i < total;
         i += (size_t)gridDim.x * blockDim.x) {
        float4 v = x4[i];
        __nv_bfloat162* hp = (__nv_bfloat162*)(g_hi + i * 4);
        hp[0] = __nv_bfloat162(__float2bfloat16(v.x), __float2bfloat16(v.y));
        hp[1] = __nv_bfloat162(__float2bfloat16(v.z), __float2bfloat16(v.w));
    }
}

// ==========================================================================
// templated bf16-split NT mma kernel over lower tile pairs:
// NPROD=1: acc = Ahi*Bhi^T (gram)  NPROD=3: + Ahi*Blo^T + Alo*Bhi^T (SYRK)
// MODE=0:  C = clip(acc*scale, -1, 1);   MODE=1: C -= acc
// ==========================================================================
#define BKG 32
#define GTILE_B (128 * 40 * 2)
#define GRAM_SMEM (2 * 4 * GTILE_B)

__device__ __forceinline__ void ldsm_x4(uint32_t* r, uint32_t addr) {
    asm volatile("ldmatrix.sync.aligned.m8n8.x4.shared.b16 {%0,%1,%2,%3}, [%4];"
                 : "=r"(r[0]), "=r"(r[1]), "=r"(r[2]), "=r"(r[3]) : "r"(addr));
}
__device__ __forceinline__ void ldsm_x2(uint32_t* r, uint32_t addr) {
    asm volatile("ldmatrix.sync.aligned.m8n8.x2.shared.b16 {%0,%1}, [%2];"
                 : "=r"(r[0]), "=r"(r[1]) : "r"(addr));
}
__device__ __forceinline__ void ldsm_x2_trans(uint32_t* r, uint32_t addr) {
    asm volatile("ldmatrix.sync.aligned.m8n8.x2.trans.shared.b16 {%0,%1}, [%2];"
                 : "=r"(r[0]), "=r"(r[1]) : "r"(addr));
}
__device__ __forceinline__ void mma_bf16(float* d, const uint32_t* a,
                                         const uint32_t* b) {
    asm volatile(
        "mma.sync.aligned.m16n8k16.row.col.f32.bf16.bf16.f32 "
        "{%0,%1,%2,%3}, {%4,%5,%6,%7}, {%8,%9}, {%0,%1,%2,%3};"
        : "+f"(d[0]), "+f"(d[1]), "+f"(d[2]), "+f"(d[3])
        : "r"(a[0]), "r"(a[1]), "r"(a[2]), "r"(a[3]), "r"(b[0]), "r"(b[1]));
}
#define CP_ASYNC(dst, src) \
    asm volatile("cp.async.cg.shared.global [%0], [%1], 16;" \
                 :: "r"(dst), "l"(src))
#define CP_COMMIT() asm volatile("cp.async.commit_group;" ::: "memory")

template <int NPROD, int MODE>
__global__ __launch_bounds__(256, 1)
void mma_nt_kernel(const __nv_bfloat16* __restrict__ Ahi,
                   const __nv_bfloat16* __restrict__ Alo,
                   const __nv_bfloat16* __restrict__ Bhi,
                   const __nv_bfloat16* __restrict__ Blo,
                   size_t lda, float* __restrict__ Cbase, int ldc,
                   int K, float scale)
{
    extern __shared__ char dsm[];
    uint32_t sbase = smem_u32(dsm);

    int tid  = threadIdx.x;
    int wid  = tid >> 5;
    int lane = tid & 31;

    int t = blockIdx.x;
    int bi = (int)((sqrtf(8.f * (float)t + 1.f) - 1.f) * 0.5f);
    while ((bi + 1) * (bi + 2) / 2 <= t) bi++;
    while (bi * (bi + 1) / 2 > t) bi--;
    int bj = t - bi * (bi + 1) / 2;

    const __nv_bfloat16* srcs[4] = {
        Ahi + (size_t)bi * 128 * lda,
        Alo + (size_t)bi * 128 * lda,
        Bhi + (size_t)bj * 128 * lda,
        Blo + (size_t)bj * 128 * lda
    };

    int m0w = (wid & 1) * 64;
    int n0w = (wid >> 1) * 32;

    float acc[4][4][4];
#pragma unroll
    for (int im = 0; im < 4; im++)
#pragma unroll
        for (int jn = 0; jn < 4; jn++)
#pragma unroll
            for (int e = 0; e < 4; e++) acc[im][jn][e] = 0.f;

    const int S = K / BKG;

    {
#pragma unroll
        for (int it = 0; it < 8; it++) {
            int idx = tid + it * 256;
            int tile = idx >> 9;
            int rem = idx & 511;
            int r = rem >> 2, ch = rem & 3;
            if (NPROD == 1 && (tile & 1)) continue;
            if (NPROD == 2 && tile == 1) continue;
            uint32_t dst = sbase + (uint32_t)tile * GTILE_B + r * 80 + ch * 16;
            CP_ASYNC(dst, srcs[tile] + (size_t)r * lda + ch * 8);
        }
        CP_COMMIT();
    }

#pragma unroll 1
    for (int s = 0; s < S; s++) {
        if (s + 1 < S) {
            int k0 = (s + 1) * BKG;
            uint32_t boff = (uint32_t)((s + 1) & 1) * (4 * GTILE_B);
#pragma unroll
            for (int it = 0; it < 8; it++) {
                int idx = tid + it * 256;
                int tile = idx >> 9;
                int rem = idx & 511;
                int r = rem >> 2, ch = rem & 3;
                if (NPROD == 1 && (tile & 1)) continue;
                if (NPROD == 2 && tile == 1) continue;
                uint32_t dst = sbase + boff + (uint32_t)tile * GTILE_B +
                               r * 80 + ch * 16;
                CP_ASYNC(dst, srcs[tile] + (size_t)r * lda + k0 + ch * 8);
            }
            CP_COMMIT();
            asm volatile("cp.async.wait_group 1;" ::: "memory");
        } else {
            asm volatile("cp.async.wait_group 0;" ::: "memory");
        }
        __syncthreads();

        uint32_t buf = sbase + (uint32_t)(s & 1) * (4 * GTILE_B);
        uint32_t Ahi_b = buf;
        uint32_t Alo_b = buf + GTILE_B;
        uint32_t Bhi_b = buf + 2 * GTILE_B;
        uint32_t Blo_b = buf + 3 * GTILE_B;

#pragma unroll
        for (int ks = 0; ks < 2; ks++) {
            int kof = ks * 16;
            int arow = lane & 15;
            int acol = kof + 8 * (lane >> 4);
            uint32_t ah[4][4], al[4][4];
#pragma unroll
            for (int im = 0; im < 4; im++) {
                uint32_t ro = (uint32_t)(m0w + im * 16 + arow) * 80 + acol * 2;
                ldsm_x4(ah[im], Ahi_b + ro);
                if (NPROD == 3) ldsm_x4(al[im], Alo_b + ro);
            }
            int brow = lane & 7;
            int bcol = kof + 8 * ((lane >> 3) & 1);
            uint32_t bh[4][2], bl[4][2];
#pragma unroll
            for (int jn = 0; jn < 4; jn++) {
                uint32_t ro = (uint32_t)(n0w + jn * 8 + brow) * 80 + bcol * 2;
                ldsm_x2(bh[jn], Bhi_b + ro);
                if (NPROD >= 2) ldsm_x2(bl[jn], Blo_b + ro);
            }
#pragma unroll
            for (int im = 0; im < 4; im++)
#pragma unroll
                for (int jn = 0; jn < 4; jn++) {
                    mma_bf16(acc[im][jn], ah[im], bh[jn]);
                    if (NPROD >= 2) mma_bf16(acc[im][jn], ah[im], bl[jn]);
                    if (NPROD == 3) mma_bf16(acc[im][jn], al[im], bh[jn]);
                }
        }
        __syncthreads();
    }

#pragma unroll
    for (int im = 0; im < 4; im++) {
        int row = bi * 128 + m0w + im * 16 + (lane >> 2);
#pragma unroll
        for (int jn = 0; jn < 4; jn++) {
            int col = bj * 128 + n0w + jn * 8 + (lane & 3) * 2;
            float* p0 = Cbase + (size_t)row * ldc + col;
            float* p1 = Cbase + (size_t)(row + 8) * ldc + col;
            if (MODE == 0) {
                p0[0] = fminf(fmaxf(acc[im][jn][0] * scale, -1.f), 1.f);
                p0[1] = fminf(fmaxf(acc[im][jn][1] * scale, -1.f), 1.f);
                p1[0] = fminf(fmaxf(acc[im][jn][2] * scale, -1.f), 1.f);
                p1[1] = fminf(fmaxf(acc[im][jn][3] * scale, -1.f), 1.f);
            } else {
                p0[0] -= acc[im][jn][0];
                p0[1] -= acc[im][jn][1];
                p1[0] -= acc[im][jn][2];
                p1[1] -= acc[im][jn][3];
            }
        }
    }
}

// ==========================================================================
// batched NN mma GEMM with on-the-fly fp32 -> bf16 hi/lo split (3 products)
// C = alpha * A[M,K] * B[K,N]  (beta = 0), 128x128 tiles, BK=32
// MASKA: A is diag-aligned lower-triangular -> zero elements with col > row
// MASKB: same for B
// B fragments via ldmatrix.x2.trans on row-major B tiles.
// ==========================================================================
#define NNT_A 10240                  // 128 rows * 80 B  (32 bf16 + pad)
#define NNT_B 8704                   // 32 rows * 272 B  (128 bf16 + pad)
#define NN_STAGE (2 * NNT_A + 2 * NNT_B)
#define NN_SMEM (2 * NN_STAGE)       // 75776 B

template <int MASKA, int MASKB>
__global__ __launch_bounds__(256, 1)
void gemm_nn_mma(const float* __restrict__ A, size_t strA, int lda,
                 const float* __restrict__ B, size_t strB, int ldb,
                 float* __restrict__ C, size_t strC, int ldc,
                 int K, float alpha)
{
    A += (size_t)blockIdx.z * strA;
    B += (size_t)blockIdx.z * strB;
    C += (size_t)blockIdx.z * strC;

    extern __shared__ char dsm[];
    uint32_t sbase = smem_u32(dsm);

    int tid = threadIdx.x, wid = tid >> 5, lane = tid & 31;
    int bi = blockIdx.y, bj = blockIdx.x;
    int m0w = (wid & 1) * 64;
    int n0w = (wid >> 1) * 32;

    float acc[4][4][4];
#pragma unroll
    for (int im = 0; im < 4; im++)
#pragma unroll
        for (int jn = 0; jn < 4; jn++)
#pragma unroll
            for (int e = 0; e < 4; e++) acc[im][jn][e] = 0.f;

    const int S = K / 32;

    // per-thread load slots
    int ar_ = tid >> 3, af_ = tid & 7;         // A: 2 rows per thread pass
    int bk_ = tid >> 3, bf_ = tid & 7;         // B: kk row, 4-float chunks

    float4 ra[4], rb[4];

    // ---- load stage s into registers ----
    auto ldreg = [&](int s) {
#pragma unroll
        for (int it = 0; it < 4; it++) {
            int idx = tid + it * 256;            // A: 1024 float4s
            int r = idx >> 3, f = idx & 7;
            float4 v = *(const float4*)(A + (size_t)(bi * 128 + r) * lda +
                                        s * 32 + f * 4);
            if (MASKA) {
                int row = bi * 128 + r;
                int cb = s * 32 + f * 4;
                if (cb + 0 > row) v.x = 0.f;
                if (cb + 1 > row) v.y = 0.f;
                if (cb + 2 > row) v.z = 0.f;
                if (cb + 3 > row) v.w = 0.f;
            }
            ra[it] = v;
        }
#pragma unroll
        for (int it = 0; it < 4; it++) {
            int idx = tid + it * 256;            // B: 1024 float4s
            int kk = idx >> 5, f = idx & 31;
            float4 v = *(const float4*)(B + (size_t)(s * 32 + kk) * ldb +
                                        bj * 128 + f * 4);
            if (MASKB) {
                int krow = s * 32 + kk;
                int cb = bj * 128 + f * 4;
                if (cb + 0 > krow) v.x = 0.f;
                if (cb + 1 > krow) v.y = 0.f;
                if (cb + 2 > krow) v.z = 0.f;
                if (cb + 3 > krow) v.w = 0.f;
            }
            rb[it] = v;
        }
    };

    // ---- store registers into buffer b ----
    auto streg = [&](int b) {
        char* sm = dsm + (size_t)b * NN_STAGE;
#pragma unroll
        for (int it = 0; it < 4; it++) {
            int idx = tid + it * 256;
            int r = idx >> 3, f = idx & 7;
            float4 v = ra[it];
            float hx = __bfloat162float(__float2bfloat16(v.x));
            float hy = __bfloat162float(__float2bfloat16(v.y));
            float hz = __bfloat162float(__float2bfloat16(v.z));
            float hw = __bfloat162float(__float2bfloat16(v.w));
            uint2 hi = { bf2pack(v.x, v.y), bf2pack(v.z, v.w) };
            uint2 lo = { bf2pack(v.x - hx, v.y - hy),
                         bf2pack(v.z - hz, v.w - hw) };
            *(uint2*)(sm + r * 80 + f * 8)         = hi;
            *(uint2*)(sm + NNT_A + r * 80 + f * 8) = lo;
        }
#pragma unroll
        for (int it = 0; it < 4; it++) {
            int idx = tid + it * 256;
            int kk = idx >> 5, f = idx & 31;
            float4 v = rb[it];
            float hx = __bfloat162float(__float2bfloat16(v.x));
            float hy = __bfloat162float(__float2bfloat16(v.y));
            float hz = __bfloat162float(__float2bfloat16(v.z));
            float hw = __bfloat162float(__float2bfloat16(v.w));
            uint2 hi = { bf2pack(v.x, v.y), bf2pack(v.z, v.w) };
            uint2 lo = { bf2pack(v.x - hx, v.y - hy),
                         bf2pack(v.z - hz, v.w - hw) };
            *(uint2*)(sm + 2 * NNT_A + kk * 272 + f * 8)         = hi;
            *(uint2*)(sm + 2 * NNT_A + NNT_B + kk * 272 + f * 8) = lo;
        }
    };

    ldreg(0);
    streg(0);
    __syncthreads();

#pragma unroll 1
    for (int s = 0; s < S; s++) {
        if (s + 1 < S) ldreg(s + 1);

        uint32_t buf = sbase + (uint32_t)(s & 1) * NN_STAGE;
        uint32_t Ahi_b = buf;
        uint32_t Alo_b = buf + NNT_A;
        uint32_t Bhi_b = buf + 2 * NNT_A;
        uint32_t Blo_b = buf + 2 * NNT_A + NNT_B;

#pragma unroll
        for (int ks = 0; ks < 2; ks++) {
            int kof = ks * 16;
            int arow = lane & 15;
            int acol = kof + 8 * (lane >> 4);
            uint32_t ah[4][4], al[4][4];
#pragma unroll
            for (int im = 0; im < 4; im++) {
                uint32_t ro = (uint32_t)(m0w + im * 16 + arow) * 80 + acol * 2;
                ldsm_x4(ah[im], Ahi_b + ro);
                ldsm_x4(al[im], Alo_b + ro);
            }
            int l16 = lane & 15;
            int brow = kof + (l16 & 7) + 8 * (l16 >> 3);
            uint32_t bh[4][2], bl[4][2];
#pragma unroll
            for (int jn = 0; jn < 4; jn++) {
                int n0 = n0w + jn * 8;
                uint32_t ro = (uint32_t)brow * 272 + n0 * 2;
                ldsm_x2_trans(bh[jn], Bhi_b + ro);
                ldsm_x2_trans(bl[jn], Blo_b + ro);
            }
#pragma unroll
            for (int im = 0; im < 4; im++)
#pragma unroll
                for (int jn = 0; jn < 4; jn++) {
                    mma_bf16(acc[im][jn], ah[im], bh[jn]);
                    mma_bf16(acc[im][jn], ah[im], bl[jn]);
                    mma_bf16(acc[im][jn], al[im], bh[jn]);
                }
        }

        if (s + 1 < S) {
            streg((s + 1) & 1);   // other buffer: no pre-sync needed
        }
        __syncthreads();
    }

#pragma unroll
    for (int im = 0; im < 4; im++) {
        int row = bi * 128 + m0w + im * 16 + (lane >> 2);
#pragma unroll
        for (int jn = 0; jn < 4; jn++) {
            int col = bj * 128 + n0w + jn * 8 + (lane & 3) * 2;
            C[(size_t)row * ldc + col]           = alpha * acc[im][jn][0];
            C[(size_t)row * ldc + col + 1]       = alpha * acc[im][jn][1];
            C[(size_t)(row + 8) * ldc + col]     = alpha * acc[im][jn][2];
            C[(size_t)(row + 8) * ldc + col + 1] = alpha * acc[im][jn][3];
        }
    }
}

// ==========================================================================
__global__ void diag_kernel()
{
    int i = blockIdx.x * blockDim.x + threadIdx.x;
    if (i < N) g_diag[i] = g_S[(size_t)i * N + i];
}

__global__ void step_kernel(const float* __restrict__ alpha_p)
{
    int j = blockIdx.x * 32 + threadIdx.x;
    int i = blockIdx.y * 8 + threadIdx.y;
    if (i >= N || j > i) return;
    float a  = *alpha_p;
    float a2 = a * a;
    float cross = sqrtf(g_diag[i] * g_diag[j]);
    float s = g_S[(size_t)i * N + j];
    float m = fminf(fmaxf(s / cross, -1.f), 1.f);
    float q = 1.f - m * m;
    float sq, ac;
    if (q > 0.f) { sq = sqrtf(q); ac = acosf(m); }
    else         { sq = 0.f;      ac = (m > 0.f) ? 0.f : PI_F; }
    float f  = (sq + m * (PI_F - ac)) / PI_F;
    float ts = cross * f;
    float ov = (s + a2 * ts) / (1.f + a2);
    g_S[(size_t)i * N + j] = fminf(fmaxf(ov, -1.f), 1.f);
}

// ==========================================================================
// panel factorization + inversion of 128x128 diag block (512 threads).
// ==========================================================================
#define PT 512
__global__ __launch_bounds__(PT, 1)
void potrf_invert(int kb)
{
    extern __shared__ float sh[];
    float* A = sh;                 // NB x NB stride LDA (L, lower)
    float* W = sh + NB * LDA;      // NB x NB stride LDA (inv(L), lower)
    __shared__ float Ts[3 * 1056];
    int tid = threadIdx.x;
    int base = kb * NB;

    for (int idx = tid; idx < NB * 32; idx += PT) {
        int i = idx >> 5, j4 = (idx & 31) << 2;
        float4 v = *(const float4*)&g_S[(size_t)(base + i) * N + base + j4];
        A[i * LDA + j4 + 0] = v.x;
        A[i * LDA + j4 + 1] = v.y;
        A[i * LDA + j4 + 2] = v.z;
        A[i * LDA + j4 + 3] = v.w;
    }
    __syncthreads();

    for (int p = 0; p < 4; p++) {
        int off = p * 32;

        if (tid < 32) {
            const unsigned FULL = 0xffffffffu;
            int r = tid;
            float ar[32];
#pragma unroll
            for (int t = 0; t < 32; t++)
                ar[t] = (t <= r) ? A[(off + r) * LDA + off + t] : 0.f;
            float rs_reg = 0.f;
#pragma unroll
            for (int j = 0; j < 32; j++) {
                float d   = __shfl_sync(FULL, ar[j], j);
                float rsj = rsqrtf(d);
                float lj  = ar[j] * rsj;
                ar[j] = lj;
                if (r == j) rs_reg = rsj;
#pragma unroll
                for (int t = j + 1; t < 32; t++) {
                    float ltj = __shfl_sync(FULL, lj, t);
                    ar[t] -= lj * ltj;
                }
            }
            int c = r;
            float w[32];
#pragma unroll
            for (int t = 0; t < 32; t++) w[t] = 0.f;
#pragma unroll
            for (int i = 0; i < 32; i++) {
                float s = (i == c) ? 1.f : 0.f;
#pragma unroll
                for (int t = 0; t < i; t++) {
                    float lit = __shfl_sync(FULL, ar[t], i);
                    s -= lit * w[t];
                }
                float rsi = __shfl_sync(FULL, rs_reg, i);
                w[i] = (i >= c) ? s * rsi : 0.f;
            }
#pragma unroll
            for (int t = 0; t < 32; t++)
                if (t <= r) A[(off + r) * LDA + off + t] = ar[t];
#pragma unroll
            for (int i = 0; i < 32; i++)
                W[(off + i) * LDA + off + c] = w[i];
        }
        __syncthreads();

        int nr = NB - off - 32;
        if (nr > 0) {
            int ntr = (nr >> 2) * 8;
            float acc[4][4];
            int tr = 0, tc = 0;
            if (tid < ntr) {
                tr = (tid >> 3) * 4;
                tc = (tid & 7) * 4;
#pragma unroll
                for (int r = 0; r < 4; r++)
#pragma unroll
                    for (int cidx = 0; cidx < 4; cidx++) acc[r][cidx] = 0.f;
#pragma unroll 8
                for (int k = 0; k < 32; k++) {
                    float av[4], wv[4];
#pragma unroll
                    for (int r = 0; r < 4; r++)
                        av[r] = A[(off + 32 + tr + r) * LDA + off + k];
#pragma unroll
                    for (int cidx = 0; cidx < 4; cidx++)
                        wv[cidx] = W[(off + tc + cidx) * LDA + off + k];
#pragma unroll
                    for (int r = 0; r < 4; r++)
#pragma unroll
                        for (int cidx = 0; cidx < 4; cidx++)
                            acc[r][cidx] += av[r] * wv[cidx];
                }
            }
            __syncthreads();
            if (tid < ntr) {
#pragma unroll
                for (int r = 0; r < 4; r++)
#pragma unroll
                    for (int cidx = 0; cidx < 4; cidx++)
                        A[(off + 32 + tr + r) * LDA + off + tc + cidx] =
                            acc[r][cidx];
            }
            __syncthreads();

            int nt = nr >> 2;
            int ntot = nt * (nt + 1) / 2;
            for (int tId = tid; tId < ntot; tId += PT) {
                int ti = (int)((sqrtf(8.f * (float)tId + 1.f) - 1.f) * 0.5f);
                while ((ti + 1) * (ti + 2) / 2 <= tId) ti++;
                while (ti * (ti + 1) / 2 > tId) ti--;
                int tj = tId - ti * (ti + 1) / 2;
                int i0 = off + 32 + ti * 4;
                int t0 = off + 32 + tj * 4;
                float a2[4][4];
#pragma unroll
                for (int r = 0; r < 4; r++)
#pragma unroll
                    for (int cidx = 0; cidx < 4; cidx++) a2[r][cidx] = 0.f;
#pragma unroll 8
                for (int k = 0; k < 32; k++) {
                    float av[4], bv[4];
#pragma unroll
                    for (int r = 0; r < 4; r++)
                        av[r] = A[(i0 + r) * LDA + off + k];
#pragma unroll
                    for (int cidx = 0; cidx < 4; cidx++)
                        bv[cidx] = A[(t0 + cidx) * LDA + off + k];
#pragma unroll
                    for (int r = 0; r < 4; r++)
#pragma unroll
                        for (int cidx = 0; cidx < 4; cidx++)
                            a2[r][cidx] += av[r] * bv[cidx];
                }
#pragma unroll
                for (int r = 0; r < 4; r++)
#pragma unroll
                    for (int cidx = 0; cidx < 4; cidx++) {
                        int ii = i0 + r, tt = t0 + cidx;
                        if (tt <= ii) A[ii * LDA + tt] -= a2[r][cidx];
                    }
            }
            __syncthreads();
        }
    }

    for (int ib = 1; ib < 4; ib++) {
        for (int tId = tid; tId < ib * 64; tId += PT) {
            int j = tId >> 6;
            int e = tId & 63;
            int r0 = (e >> 3) * 4, c0 = (e & 7) * 4;
            float acc[4][4];
#pragma unroll
            for (int r = 0; r < 4; r++)
#pragma unroll
                for (int cidx = 0; cidx < 4; cidx++) acc[r][cidx] = 0.f;
            for (int tb = j; tb < ib; tb++) {
#pragma unroll 8
                for (int k = 0; k < 32; k++) {
                    float lv[4], wv[4];
#pragma unroll
                    for (int r = 0; r < 4; r++)
                        lv[r] = A[(32 * ib + r0 + r) * LDA + 32 * tb + k];
#pragma unroll
                    for (int cidx = 0; cidx < 4; cidx++)
                        wv[cidx] = W[(32 * tb + k) * LDA + 32 * j + c0 + cidx];
#pragma unroll
                    for (int r = 0; r < 4; r++)
#pragma unroll
                        for (int cidx = 0; cidx < 4; cidx++)
                            acc[r][cidx] += lv[r] * wv[cidx];
                }
            }
#pragma unroll
            for (int r = 0; r < 4; r++)
#pragma unroll
                for (int cidx = 0; cidx < 4; cidx++)
                    Ts[j * 1056 + (r0 + r) * 33 + c0 + cidx] = acc[r][cidx];
        }
        __syncthreads();
        for (int tId = tid; tId < ib * 64; tId += PT) {
            int j = tId >> 6;
            int e = tId & 63;
            int r0 = (e >> 3) * 4, c0 = (e & 7) * 4;
            float acc[4][4];
#pragma unroll
            for (int r = 0; r < 4; r++)
#pragma unroll
                for (int cidx = 0; cidx < 4; cidx++) acc[r][cidx] = 0.f;
#pragma unroll 8
            for (int k = 0; k < 32; k++) {
                float wv[4], tv[4];
#pragma unroll
                for (int r = 0; r < 4; r++)
                    wv[r] = W[(32 * ib + r0 + r) * LDA + 32 * ib + k];
#pragma unroll
                for (int cidx = 0; cidx < 4; cidx++)
                    tv[cidx] = Ts[j * 1056 + k * 33 + c0 + cidx];
#pragma unroll
                for (int r = 0; r < 4; r++)
#pragma unroll
                    for (int cidx = 0; cidx < 4; cidx++)
                        acc[r][cidx] += wv[r] * tv[cidx];
            }
#pragma unroll
            for (int r = 0; r < 4; r++)
#pragma unroll
                for (int cidx = 0; cidx < 4; cidx++)
                    W[(32 * ib + r0 + r) * LDA + 32 * j + c0 + cidx] =
                        -acc[r][cidx];
        }
        __syncthreads();
    }

    for (int idx = tid; idx < NB * NB; idx += PT) {
        int i = idx >> 7, j = idx & 127;
        if (j <= i) g_S[(size_t)(base + i) * N + base + j] = A[i * LDA + j];
        g_invD[(size_t)kb * NB * NB + idx] =
            ((j >> 5) <= (i >> 5)) ? W[i * LDA + j] : 0.f;
    }
}

// ==========================================================================
// TRSM panel GEMM: C = A * B^T (64x64 tiles); writes fp32 L into S and
// bf16 hi/lo split panels for the mma SYRK.
// ==========================================================================
__global__ __launch_bounds__(256, 2)
void gemm_nt_split(const float* __restrict__ A, int lda,
                   const float* __restrict__ B, int ldb,
                   float* __restrict__ Cs, int ldcs,
                   __nv_bfloat16* __restrict__ Phi,
                   __nv_bfloat16* __restrict__ Plo, int K)
{
    __shared__ float As[16][64];
    __shared__ float Bs[16][64];
    int bi = blockIdx.y, bj = blockIdx.x;
    int tid = threadIdx.x;
    int tx = tid & 15, ty = tid >> 4;

    const float* Ab = A + (size_t)(bi * 64) * lda;
    const float* Bb = B + (size_t)(bj * 64) * ldb;

    int arow = tid >> 2, akk = (tid & 3) << 2;

    float acc[4][4];
#pragma unroll
    for (int i = 0; i < 4; i++)
#pragma unroll
        for (int j = 0; j < 4; j++) acc[i][j] = 0.f;

    for (int k0 = 0; k0 < K; k0 += 16) {
        float4 va = *(const float4*)(Ab + (size_t)arow * lda + k0 + akk);
        float4 vb = *(const float4*)(Bb + (size_t)arow * ldb + k0 + akk);
        As[akk + 0][arow] = va.x; As[akk + 1][arow] = va.y;
        As[akk + 2][arow] = va.z; As[akk + 3][arow] = va.w;
        Bs[akk + 0][arow] = vb.x; Bs[akk + 1][arow] = vb.y;
        Bs[akk + 2][arow] = vb.z; Bs[akk + 3][arow] = vb.w;
        __syncthreads();
#pragma unroll
        for (int kk = 0; kk < 16; kk++) {
            float4 a = *(const float4*)&As[kk][ty * 4];
            float4 b = *(const float4*)&Bs[kk][tx * 4];
            float av[4] = {a.x, a.y, a.z, a.w};
            float bv[4] = {b.x, b.y, b.z, b.w};
#pragma unroll
            for (int i = 0; i < 4; i++)
#pragma unroll
                for (int j = 0; j < 4; j++)
                    acc[i][j] += av[i] * bv[j];
        }
        __syncthreads();
    }

#pragma unroll
    for (int i = 0; i < 4; i++) {
        int row = bi * 64 + ty * 4 + i;
#pragma unroll
        for (int j = 0; j < 4; j++) {
            int col = bj * 64 + tx * 4 + j;
            float v = acc[i][j];
            Cs[(size_t)row * ldcs + col] = v;
            __nv_bfloat16 h = __float2bfloat16(v);
            Phi[(size_t)row * NB + col] = h;
            Plo[(size_t)row * NB + col] =
                __float2bfloat16(v - __bfloat162float(h));
        }
    }
}

// ==========================================================================
__global__ void zero_kernel(float* p, int n)
{
    for (int i = blockIdx.x * blockDim.x + threadIdx.x; i < n;
         i += gridDim.x * blockDim.x)
        p[i] = 0.f;
}

__global__ void copy_diag_kernel()
{
    int kb = blockIdx.y;
    int idx = blockIdx.x * 256 + threadIdx.x;
    int i = idx >> 7, j = idx & 127;
    g_W[(size_t)(kb * NB + i) * N + kb * NB + j] =
        g_invD[(size_t)kb * NB * NB + idx];
}

// ==========================================================================
// fused reduction over lower-triangular W:
//   trace(inv) = ||W||_F^2,  proj = sum_r (W_row_r . c)^2
// ==========================================================================
__global__ void reduce_kernel(const float* __restrict__ c)
{
    __shared__ float r2[256], ry[256];
    int r = blockIdx.x;
    const float* row = g_W + (size_t)r * N;
    float s2 = 0.f, sy = 0.f;
    for (int j = threadIdx.x; j <= r; j += 256) {
        float v = row[j];
        s2 += v * v;
        sy += v * c[j];
    }
    r2[threadIdx.x] = s2; ry[threadIdx.x] = sy;
    __syncthreads();
    for (int o = 128; o > 0; o >>= 1) {
        if (threadIdx.x < o) {
            r2[threadIdx.x] += r2[threadIdx.x + o];
            ry[threadIdx.x] += ry[threadIdx.x + o];
        }
        __syncthreads();
    }
    if (threadIdx.x == 0) {
        atomicAdd(&g_scal[0], r2[0]);
        float y = ry[0];
        atomicAdd(&g_scal[1], y * y);
    }
}

__global__ void final_kernel(float* out)
{
    __shared__ float red[256];
    float s = 0.f;
    for (int i = threadIdx.x; i < N; i += 256)
        s += logf(g_S[(size_t)i * N + i]);
    red[threadIdx.x] = s; __syncthreads();
    for (int o = 128; o > 0; o >>= 1) {
        if (threadIdx.x < o) red[threadIdx.x] += red[threadIdx.x + o];
        __syncthreads();
    }
    if (threadIdx.x == 0) {
        float nrd = expf(red[0] * (2.0f / (float)N));
        out[0] = (float)N / 5.0f +
                 nrd * ((0.5f - 1.0f / PI_F) * g_scal[0] + g_scal[1] / PI_F);
    }
}

// ==========================================================================
// host orchestration
// ==========================================================================
extern "C" void kernel_launch(void* const* d_in, const int* in_sizes, int n_in,
                              void* d_out, int out_size)
{
    (void)in_sizes; (void)n_in; (void)out_size;
    const float* x     = (const float*)d_in[0];
    const float* c     = (const float*)d_in[1];
    const float* alpha = (const float*)d_in[2];
    float* out = (float*)d_out;

    float *Sp, *Wp, *iDp, *T2p, *scalp;
    __nv_bfloat16 *hip, *lop, *Phip, *Plop;
    cudaGetSymbolAddress((void**)&Sp,    g_S);
    cudaGetSymbolAddress((void**)&Wp,    g_W);
    cudaGetSymbolAddress((void**)&iDp,   g_invD);
    cudaGetSymbolAddress((void**)&T2p,   g_T2);
    cudaGetSymbolAddress((void**)&scalp, g_scal);
    cudaGetSymbolAddress((void**)&hip,   g_hi);
    cudaGetSymbolAddress((void**)&lop,   g_lo);
    cudaGetSymbolAddress((void**)&Phip,  g_Phi);
    cudaGetSymbolAddress((void**)&Plop,  g_Plo);

    int potrf_smem = 2 * NB * LDA * (int)sizeof(float);
    cudaFuncSetAttribute(potrf_invert,
                         cudaFuncAttributeMaxDynamicSharedMemorySize,
                         potrf_smem);
    cudaFuncSetAttribute(mma_nt_kernel<1, 0>,
                         cudaFuncAttributeMaxDynamicSharedMemorySize,
                         GRAM_SMEM);
    cudaFuncSetAttribute(mma_nt_kernel<3, 1>,
                         cudaFuncAttributeMaxDynamicSharedMemorySize,
                         GRAM_SMEM);
    cudaFuncSetAttribute(gemm_nn_mma<1, 0>,
                         cudaFuncAttributeMaxDynamicSharedMemorySize,
                         NN_SMEM);
    cudaFuncSetAttribute(gemm_nn_mma<0, 1>,
                         cudaFuncAttributeMaxDynamicSharedMemorySize,
                         NN_SMEM);

    // 1. gram via pure-hi bf16 mma (1 product)
    split_kernel<<<4096, 256>>>(x);
    mma_nt_kernel<1, 0><<<NBLK * (NBLK + 1) / 2, 256, GRAM_SMEM>>>(
        hip, lop, hip, lop, D, Sp, N, D, 1.0f / (float)D);

    // 2. arc-cosine kernel step
    diag_kernel<<<N / 256, 256>>>();
    step_kernel<<<dim3(N / 32, N / 8), dim3(32, 8)>>>(alpha);

    // 3. blocked Cholesky (in place, lower)
    for (int k = 0; k < NBLK; k++) {
        potrf_invert<<<1, PT, potrf_smem>>>(k);
        if (k < NBLK - 1) {
            int rows = (NBLK - 1 - k) * NB;
            gemm_nt_split<<<dim3(2, rows / 64), 256>>>(
                Sp + (size_t)(k + 1) * NB * N + (size_t)k * NB, N,
                iDp + (size_t)k * NB * NB, NB,
                Sp + (size_t)(k + 1) * NB * N + (size_t)k * NB, N,
                Phip, Plop, NB);
            int T2 = NBLK - 1 - k;
            mma_nt_kernel<3, 1><<<T2 * (T2 + 1) / 2, 256, GRAM_SMEM>>>(
                Phip, Plop, Phip, Plop, NB,
                Sp + (size_t)(k + 1) * NB * N + (size_t)(k + 1) * NB, N,
                NB, 1.0f);
        }
    }

    // 4. divide & conquer triangular inversion: W = L^{-1} (mma, masked
    //    triangular operand loads -> no W zeroing needed)
    copy_diag_kernel<<<dim3(64, NBLK), 256>>>();
    for (int lev = 0; lev < 4; lev++) {
        int s = 128 << lev;
        int pairs = N / (2 * s);
        size_t strW = (size_t)2 * s * (N + 1);
        // T = W11 * L10   (W11 lower-triangular -> MASKA)
        gemm_nn_mma<1, 0><<<dim3(s / 128, s / 128, pairs), 256, NN_SMEM>>>(
            Wp + (size_t)s * N + s, strW, N,
            Sp + (size_t)s * N,     strW, N,
            T2p, (size_t)s * s, s,
            s, 1.0f);
        // W10 = -T * W00  (W00 lower-triangular -> MASKB)
        gemm_nn_mma<0, 1><<<dim3(s / 128, s / 128, pairs), 256, NN_SMEM>>>(
            T2p, (size_t)s * s, s,
            Wp, strW, N,
            Wp + (size_t)s * N, strW, N,
            s, -1.0f);
    }

    // 5. fused reductions + final scalar
    zero_kernel<<<1, 32>>>(scalp, 4);
    reduce_kernel<<<N, 256>>>(c);
    final_kernel<<<1, 256>>>(out);
}